// round 1
// baseline (speedup 1.0000x reference)
#include <cuda_runtime.h>
#include <math.h>

#define NPG 23
#define NF 11
#define HID 48
#define HEADS 4
#define C1 192          // HEADS*HID
#define NGRAPH 1024     // B*T
#define H1S 193         // padded row stride for 192-wide tiles
#define GRUH 64
#define G3 192          // 3*GRUH
#define TT 16
#define BB 64
#define FRAME 96

__device__ float g_frames[NGRAPH * FRAME];

// ---------------------------------------------------------------------------
// Kernel 1: fused GAT1 + GAT2 + pooling, one block per 23-node group.
// ---------------------------------------------------------------------------
__global__ void gat_kernel(const float* __restrict__ x,
                           const float* __restrict__ W1,
                           const float* __restrict__ as1,
                           const float* __restrict__ ad1,
                           const float* __restrict__ b1,
                           const float* __restrict__ W2,
                           const float* __restrict__ as2,
                           const float* __restrict__ ad2,
                           const float* __restrict__ b2)
{
    extern __shared__ float sm[];
    float* xs    = sm;                 // 256   (23*11 = 253)
    float* W1s   = xs    + 256;        // 2112
    float* as1s  = W1s   + 2112;       // 192
    float* ad1s  = as1s  + 192;        // 192
    float* b1s   = ad1s  + 192;        // 192
    float* W2s   = b1s   + 192;        // 9216
    float* as2s  = W2s   + 9216;       // 48
    float* ad2s  = as2s  + 48;         // 48
    float* b2s   = ad2s  + 48;         // 48
    float* h1    = b2s   + 48;         // 23*193 = 4439
    float* o1    = h1    + 4439;       // 4439
    float* als   = o1    + 4439;       // 96
    float* ald   = als   + 96;         // 96
    float* alpha = ald   + 96;         // 4*23*23 = 2116
    float* h2    = alpha + 2116;       // 23*48 = 1104
    float* al2s  = h2    + 1104;       // 32
    float* al2d  = al2s  + 32;         // 32
    float* alpha2= al2d  + 32;         // 544 (23*23=529)
    float* o2    = alpha2+ 544;        // 1104

    const int g   = blockIdx.x;
    const int tid = threadIdx.x;
    const float* xg = x + (size_t)g * NPG * NF;

    // ---- cooperative loads ----
    for (int i = tid; i < NPG * NF; i += 256) xs[i] = xg[i];
    for (int i = tid; i < NF * C1;  i += 256) W1s[i] = W1[i];
    for (int i = tid; i < C1;       i += 256) {
        as1s[i] = as1[i]; ad1s[i] = ad1[i]; b1s[i] = b1[i];
    }
    for (int i = tid; i < C1 * HID; i += 256) W2s[i] = W2[i];
    if (tid < HID) { as2s[tid] = as2[tid]; ad2s[tid] = ad2[tid]; b2s[tid] = b2[tid]; }
    __syncthreads();

    // ---- h1 = x @ W1  (23 x 192) ----
    for (int idx = tid; idx < NPG * C1; idx += 256) {
        int i = idx / C1, c = idx - i * C1;
        float acc = 0.f;
        #pragma unroll
        for (int f = 0; f < NF; f++) acc += xs[i * NF + f] * W1s[f * C1 + c];
        h1[i * H1S + c] = acc;
    }
    __syncthreads();

    // ---- attention logits per (node, head) ----
    if (tid < NPG * HEADS) {
        int i = tid >> 2, hd = tid & 3;
        float ss = 0.f, dd = 0.f;
        #pragma unroll
        for (int k = 0; k < HID; k++) {
            float v = h1[i * H1S + hd * HID + k];
            ss += v * as1s[hd * HID + k];
            dd += v * ad1s[hd * HID + k];
        }
        als[tid] = ss; ald[tid] = dd;
    }
    __syncthreads();

    // ---- softmax over the 23 sources for each (dst, head) ----
    if (tid < NPG * HEADS) {
        int j = tid >> 2, hd = tid & 3;
        float adj = ald[j * 4 + hd];
        float e[NPG];
        float m = -1e30f;
        #pragma unroll
        for (int i = 0; i < NPG; i++) {
            float v = als[i * 4 + hd] + adj;
            v = (v > 0.f) ? v : 0.2f * v;          // leaky_relu(0.2)
            e[i] = v;
            m = fmaxf(m, v);
        }
        float s = 0.f;
        #pragma unroll
        for (int i = 0; i < NPG; i++) { float w = expf(e[i] - m); e[i] = w; s += w; }
        float inv = 1.f / (s + 1e-16f);
        #pragma unroll
        for (int i = 0; i < NPG; i++) alpha[(hd * NPG + j) * NPG + i] = e[i] * inv;
    }
    __syncthreads();

    // ---- aggregate + bias + elu -> o1 (23 x 192) ----
    for (int idx = tid; idx < NPG * C1; idx += 256) {
        int j = idx / C1, c = idx - j * C1;
        int hd = c / HID;
        const float* a = &alpha[(hd * NPG + j) * NPG];
        float acc = 0.f;
        #pragma unroll
        for (int i = 0; i < NPG; i++) acc += a[i] * h1[i * H1S + c];
        acc += b1s[c];
        o1[j * H1S + c] = (acc > 0.f) ? acc : expm1f(acc);
    }
    __syncthreads();

    // ---- h2 = o1 @ W2 (23 x 48) ----
    for (int idx = tid; idx < NPG * HID; idx += 256) {
        int i = idx / HID, k = idx - i * HID;
        float acc = 0.f;
        #pragma unroll 8
        for (int c = 0; c < C1; c++) acc += o1[i * H1S + c] * W2s[c * HID + k];
        h2[i * HID + k] = acc;
    }
    __syncthreads();

    if (tid < NPG) {
        float ss = 0.f, dd = 0.f;
        #pragma unroll
        for (int k = 0; k < HID; k++) {
            float v = h2[tid * HID + k];
            ss += v * as2s[k]; dd += v * ad2s[k];
        }
        al2s[tid] = ss; al2d[tid] = dd;
    }
    __syncthreads();

    if (tid < NPG) {
        int j = tid;
        float adj = al2d[j];
        float e[NPG];
        float m = -1e30f;
        #pragma unroll
        for (int i = 0; i < NPG; i++) {
            float v = al2s[i] + adj;
            v = (v > 0.f) ? v : 0.2f * v;
            e[i] = v; m = fmaxf(m, v);
        }
        float s = 0.f;
        #pragma unroll
        for (int i = 0; i < NPG; i++) { float w = expf(e[i] - m); e[i] = w; s += w; }
        float inv = 1.f / (s + 1e-16f);
        #pragma unroll
        for (int i = 0; i < NPG; i++) alpha2[j * NPG + i] = e[i] * inv;
    }
    __syncthreads();

    // ---- aggregate GAT2 + bias + elu -> o2 (23 x 48) ----
    for (int idx = tid; idx < NPG * HID; idx += 256) {
        int j = idx / HID, k = idx - j * HID;
        const float* a = &alpha2[j * NPG];
        float acc = 0.f;
        #pragma unroll
        for (int i = 0; i < NPG; i++) acc += a[i] * h2[i * HID + k];
        acc += b2s[k];
        o2[j * HID + k] = (acc > 0.f) ? acc : expm1f(acc);
    }
    __syncthreads();

    // ---- mean/max pooling over the 23 nodes ----
    if (tid < HID) {
        int k = tid;
        float s = 0.f, m = -1e30f;
        #pragma unroll
        for (int j = 0; j < NPG; j++) {
            float v = o2[j * HID + k];
            s += v; m = fmaxf(m, v);
        }
        g_frames[g * FRAME + k]       = s / (float)NPG;
        g_frames[g * FRAME + HID + k] = m;
    }
}

// ---------------------------------------------------------------------------
// Kernel 2: 2-layer GRU + MLP head, one block per batch row (64 blocks x 192 thr)
// gi = x @ Wih^T is precomputed for all 16 steps; only gh is recurrent.
// ---------------------------------------------------------------------------
__device__ __forceinline__ void gru_layer(const float* __restrict__ xin, int INP, int IN,
                                          const float* __restrict__ Wih,
                                          const float* __restrict__ Whh,
                                          const float* __restrict__ bih,
                                          const float* __restrict__ bhh,
                                          float* Wih_s, float* Whh_s,
                                          float* gi, float* gh, float* hbuf,
                                          float* outseq, int tid)
{
    // load + pad weights into smem (odd strides -> conflict-free)
    for (int idx = tid; idx < G3 * IN; idx += G3) {
        int r = idx / IN, c = idx - r * IN;
        Wih_s[r * (IN + 1) + c] = Wih[idx];
    }
    for (int idx = tid; idx < G3 * GRUH; idx += G3) {
        int r = idx >> 6, c = idx & 63;
        Whh_s[r * (GRUH + 1) + c] = Whh[idx];
    }
    if (tid < GRUH) hbuf[tid] = 0.f;
    __syncthreads();

    // gi for all 16 timesteps at once
    {
        float acc[TT];
        float bi = bih[tid];
        #pragma unroll
        for (int t = 0; t < TT; t++) acc[t] = bi;
        const float* wrow = Wih_s + tid * (IN + 1);
        for (int f = 0; f < IN; f++) {
            float w = wrow[f];
            #pragma unroll
            for (int t = 0; t < TT; t++) acc[t] += w * xin[t * INP + f];
        }
        #pragma unroll
        for (int t = 0; t < TT; t++) gi[t * G3 + tid] = acc[t];
    }

    // cache this thread's Whh row in registers
    float wr[GRUH];
    #pragma unroll
    for (int u = 0; u < GRUH; u++) wr[u] = Whh_s[tid * (GRUH + 1) + u];
    float bh = bhh[tid];
    __syncthreads();

    for (int t = 0; t < TT; t++) {
        float acc = bh;
        #pragma unroll
        for (int u = 0; u < GRUH; u++) acc += wr[u] * hbuf[u];
        gh[tid] = acc;
        __syncthreads();
        if (tid < GRUH) {
            float gir = gi[t * G3 + tid];
            float giz = gi[t * G3 + GRUH + tid];
            float gin = gi[t * G3 + 2 * GRUH + tid];
            float ghr = gh[tid];
            float ghz = gh[GRUH + tid];
            float ghn = gh[2 * GRUH + tid];
            float r = 1.f / (1.f + expf(-(gir + ghr)));
            float z = 1.f / (1.f + expf(-(giz + ghz)));
            float n = tanhf(gin + r * ghn);
            float hn = (1.f - z) * n + z * hbuf[tid];
            hbuf[tid] = hn;
            outseq[t * (GRUH + 1) + tid] = hn;
        }
        __syncthreads();
    }
}

__global__ void __launch_bounds__(192) gru_kernel(
    const float* __restrict__ Wih0, const float* __restrict__ Whh0,
    const float* __restrict__ bih0, const float* __restrict__ bhh0,
    const float* __restrict__ Wih1, const float* __restrict__ Whh1,
    const float* __restrict__ bih1, const float* __restrict__ bhh1,
    const float* __restrict__ Wh1,  const float* __restrict__ bh1,
    const float* __restrict__ Wh2,  const float* __restrict__ bh2,
    float* __restrict__ out)
{
    const int b = blockIdx.x;
    const int tid = threadIdx.x;

    __shared__ float xb[TT * (FRAME + 1)];   // 16 x 97
    __shared__ float seq[TT * (GRUH + 1)];   // 16 x 65
    __shared__ float hbuf[GRUH];
    __shared__ float gi[TT * G3];            // 16 x 192
    __shared__ float gh[G3];
    __shared__ float q[32];
    extern __shared__ float ws[];            // Wih_s (192x97) + Whh_s (192x65)
    float* Wih_s = ws;
    float* Whh_s = ws + G3 * (FRAME + 1);

    // load this batch row's 16 frames
    for (int idx = tid; idx < TT * FRAME; idx += G3) {
        int t = idx / FRAME, f = idx - t * FRAME;
        xb[t * (FRAME + 1) + f] = g_frames[(size_t)(b * TT + t) * FRAME + f];
    }
    __syncthreads();

    gru_layer(xb, FRAME + 1, FRAME, Wih0, Whh0, bih0, bhh0,
              Wih_s, Whh_s, gi, gh, hbuf, seq, tid);
    __syncthreads();
    gru_layer(seq, GRUH + 1, GRUH, Wih1, Whh1, bih1, bhh1,
              Wih_s, Whh_s, gi, gh, hbuf, seq, tid);
    __syncthreads();

    // MLP head: relu(last @ Wh1 + bh1) @ Wh2 + bh2
    if (tid < 32) {
        float acc = bh1[tid];
        #pragma unroll
        for (int u = 0; u < GRUH; u++) acc += hbuf[u] * Wh1[u * 32 + tid];
        q[tid] = fmaxf(acc, 0.f);
    }
    __syncthreads();
    if (tid == 0) {
        float acc = bh2[0];
        #pragma unroll
        for (int m = 0; m < 32; m++) acc += q[m] * Wh2[m];
        out[b] = acc;
    }
}

// ---------------------------------------------------------------------------
extern "C" void kernel_launch(void* const* d_in, const int* in_sizes, int n_in,
                              void* d_out, int out_size)
{
    const float* x    = (const float*)d_in[0];
    // d_in[1]=edge_index (int64), d_in[2]=batch (int64): structure is fixed, unused
    const float* W1   = (const float*)d_in[3];
    const float* as1  = (const float*)d_in[4];
    const float* ad1  = (const float*)d_in[5];
    const float* b1   = (const float*)d_in[6];
    const float* W2   = (const float*)d_in[7];
    const float* as2  = (const float*)d_in[8];
    const float* ad2  = (const float*)d_in[9];
    const float* b2   = (const float*)d_in[10];
    const float* Wih0 = (const float*)d_in[11];
    const float* Whh0 = (const float*)d_in[12];
    const float* bih0 = (const float*)d_in[13];
    const float* bhh0 = (const float*)d_in[14];
    const float* Wih1 = (const float*)d_in[15];
    const float* Whh1 = (const float*)d_in[16];
    const float* bih1 = (const float*)d_in[17];
    const float* bhh1 = (const float*)d_in[18];
    const float* Wh1  = (const float*)d_in[19];
    const float* bh1  = (const float*)d_in[20];
    const float* Wh2  = (const float*)d_in[21];
    const float* bh2  = (const float*)d_in[22];

    const int GAT_SMEM = 26320 * 4;                           // ~105 KB
    const int GRU_SMEM = (G3 * (FRAME + 1) + G3 * (GRUH + 1)) * 4;  // ~124 KB

    cudaFuncSetAttribute(gat_kernel, cudaFuncAttributeMaxDynamicSharedMemorySize, GAT_SMEM);
    cudaFuncSetAttribute(gru_kernel, cudaFuncAttributeMaxDynamicSharedMemorySize, GRU_SMEM);

    gat_kernel<<<NGRAPH, 256, GAT_SMEM>>>(x, W1, as1, ad1, b1, W2, as2, ad2, b2);
    gru_kernel<<<BB, G3, GRU_SMEM>>>(Wih0, Whh0, bih0, bhh0,
                                     Wih1, Whh1, bih1, bhh1,
                                     Wh1, bh1, Wh2, bh2, (float*)d_out);
}

// round 2
// speedup vs baseline: 1.2822x; 1.2822x over previous
#include <cuda_runtime.h>

#define NPG 23
#define NF 11
#define HID 48
#define C1 192
#define NGRAPH 1024
#define GRUH 64
#define G3 192
#define TT 16
#define BB 64
#define FRAME 96
#define ST 196           // padded float4-aligned stride for 192-wide rows

__device__ float g_frames[NGRAPH * FRAME];
__device__ float g_gi0[NGRAPH * G3];

__device__ __forceinline__ float4 ld4(const float* p) { return *(const float4*)p; }

__device__ __forceinline__ float fast_sigmoid(float x) {
    return 1.f / (1.f + __expf(-x));
}
__device__ __forceinline__ float fast_tanh(float x) {
    float e = __expf(-2.f * x);
    return (1.f - e) / (1.f + e);
}
__device__ __forceinline__ float elu1(float v) {
    return v > 0.f ? v : (__expf(v) - 1.f);
}

// ---------------------------------------------------------------------------
// Kernel 1: fused GAT1 + GAT2 + pooling. One block per 23-node group.
// Everything register-tiled with float4 (2 LDS per 4 FMA).
// ---------------------------------------------------------------------------
__global__ void __launch_bounds__(256) gat_kernel(
    const float* __restrict__ x,
    const float* __restrict__ W1,  const float* __restrict__ as1,
    const float* __restrict__ ad1, const float* __restrict__ b1,
    const float* __restrict__ W2,  const float* __restrict__ as2,
    const float* __restrict__ ad2, const float* __restrict__ b2)
{
    extern __shared__ float sm[];
    float* W1s    = sm;             // 2112
    float* W2s    = W1s  + 2112;    // 9216
    float* a1s    = W2s  + 9216;    // 192
    float* a1d    = a1s  + 192;     // 192
    float* b1s    = a1d  + 192;     // 192
    float* a2s    = b1s  + 192;     // 48
    float* a2d    = a2s  + 48;      // 48
    float* b2s    = a2d  + 48;      // 48
    float* xs     = b2s  + 48;      // 276 (23 x stride 12)
    float* h1     = xs   + 276;     // 23*196 = 4508
    float* o1     = h1   + 4508;    // 4508
    float* als    = o1   + 4508;    // 96
    float* ald    = als  + 96;      // 96
    float* alpha  = ald  + 96;      // 4*23*23 = 2116
    float* h2     = alpha+ 2116;    // 23*48 = 1104
    float* al2s   = h2   + 1104;    // 24
    float* al2d   = al2s + 24;      // 24
    float* alpha2 = al2d + 24;      // 23*24 = 552
    float* o2     = alpha2 + 552;   // 1104
    // total 26456 floats = 105824 B

    const int tid = threadIdx.x;
    const int g   = blockIdx.x;

    // ---- cooperative loads (vectorized) ----
    for (int i4 = tid; i4 < 2112 / 4; i4 += 256)
        ((float4*)W1s)[i4] = ((const float4*)W1)[i4];
    for (int i4 = tid; i4 < 9216 / 4; i4 += 256)
        ((float4*)W2s)[i4] = ((const float4*)W2)[i4];
    if (tid < 192) { a1s[tid] = as1[tid]; a1d[tid] = ad1[tid]; b1s[tid] = b1[tid]; }
    else if (tid < 240) {
        int k = tid - 192;
        a2s[k] = as2[k]; a2d[k] = ad2[k]; b2s[k] = b2[k];
    }
    const float* xg = x + (size_t)g * (NPG * NF);
    for (int i = tid; i < NPG * NF; i += 256) {
        int r = i / NF, c = i - r * NF;
        xs[r * 12 + c] = xg[i];
    }
    __syncthreads();

    // ---- h1 = x @ W1  (23 x 192), float4 outputs ----
    for (int idx = tid; idx < NPG * 48; idx += 256) {
        int i = idx / 48, c4 = idx - (idx / 48) * 48;
        const float* xr = xs + i * 12;
        float4 acc = make_float4(0.f, 0.f, 0.f, 0.f);
        #pragma unroll
        for (int f = 0; f < NF; f++) {
            float xv = xr[f];
            float4 w = ld4(W1s + f * 192 + c4 * 4);
            acc.x += xv * w.x; acc.y += xv * w.y;
            acc.z += xv * w.z; acc.w += xv * w.w;
        }
        *(float4*)(h1 + i * ST + c4 * 4) = acc;
    }
    __syncthreads();

    // ---- attention logits per (node, head) ----
    if (tid < NPG * 4) {
        int i = tid >> 2, hd = tid & 3;
        const float* hrow = h1 + i * ST + hd * HID;
        const float* sv = a1s + hd * HID;
        const float* dv = a1d + hd * HID;
        float ss = 0.f, dd = 0.f;
        #pragma unroll
        for (int k4 = 0; k4 < 12; k4++) {
            float4 v = ld4(hrow + 4 * k4);
            float4 s4 = ld4(sv + 4 * k4);
            float4 d4 = ld4(dv + 4 * k4);
            ss += v.x * s4.x + v.y * s4.y + v.z * s4.z + v.w * s4.w;
            dd += v.x * d4.x + v.y * d4.y + v.z * d4.z + v.w * d4.w;
        }
        als[tid] = ss; ald[tid] = dd;
    }
    __syncthreads();

    // ---- softmax over sources for each (dst j, head) ----
    if (tid < NPG * 4) {
        int j = tid >> 2, hd = tid & 3;
        float adj = ald[j * 4 + hd];
        float e[NPG];
        float m = -1e30f;
        #pragma unroll
        for (int i = 0; i < NPG; i++) {
            float v = als[i * 4 + hd] + adj;
            v = (v > 0.f) ? v : 0.2f * v;
            e[i] = v; m = fmaxf(m, v);
        }
        float s = 0.f;
        #pragma unroll
        for (int i = 0; i < NPG; i++) { float w = __expf(e[i] - m); e[i] = w; s += w; }
        float inv = 1.f / (s + 1e-16f);
        #pragma unroll
        for (int i = 0; i < NPG; i++) alpha[(hd * NPG + j) * NPG + i] = e[i] * inv;
    }
    __syncthreads();

    // ---- aggregate1 + bias + elu -> o1 (23 x 192) ----
    for (int idx = tid; idx < NPG * 48; idx += 256) {
        int j = idx / 48, c4 = idx - (idx / 48) * 48;
        int hd = c4 / 12;
        int c = 4 * c4;
        const float* a = alpha + (hd * NPG + j) * NPG;
        float4 acc = ld4(b1s + c);
        #pragma unroll
        for (int i = 0; i < NPG; i++) {
            float av = a[i];
            float4 h = ld4(h1 + i * ST + c);
            acc.x += av * h.x; acc.y += av * h.y;
            acc.z += av * h.z; acc.w += av * h.w;
        }
        acc.x = elu1(acc.x); acc.y = elu1(acc.y);
        acc.z = elu1(acc.z); acc.w = elu1(acc.w);
        *(float4*)(o1 + j * ST + c) = acc;
    }
    __syncthreads();

    // ---- h2 = o1 @ W2 (23 x 48) ----
    for (int idx = tid; idx < NPG * 12; idx += 256) {
        int i = idx / 12, k4 = idx - (idx / 12) * 12;
        const float* o1r = o1 + i * ST;
        const float* w = W2s + 4 * k4;
        float4 acc = make_float4(0.f, 0.f, 0.f, 0.f);
        #pragma unroll 8
        for (int c = 0; c < C1; c++) {
            float ov = o1r[c];
            float4 wv = ld4(w + c * HID);
            acc.x += ov * wv.x; acc.y += ov * wv.y;
            acc.z += ov * wv.z; acc.w += ov * wv.w;
        }
        *(float4*)(h2 + i * HID + 4 * k4) = acc;
    }
    __syncthreads();

    // ---- GAT2 logits ----
    if (tid < NPG) {
        const float* hrow = h2 + tid * HID;
        float ss = 0.f, dd = 0.f;
        #pragma unroll
        for (int k4 = 0; k4 < 12; k4++) {
            float4 v = ld4(hrow + 4 * k4);
            float4 s4 = ld4(a2s + 4 * k4);
            float4 d4 = ld4(a2d + 4 * k4);
            ss += v.x * s4.x + v.y * s4.y + v.z * s4.z + v.w * s4.w;
            dd += v.x * d4.x + v.y * d4.y + v.z * d4.z + v.w * d4.w;
        }
        al2s[tid] = ss; al2d[tid] = dd;
    }
    __syncthreads();

    if (tid < NPG) {
        int j = tid;
        float adj = al2d[j];
        float e[NPG];
        float m = -1e30f;
        #pragma unroll
        for (int i = 0; i < NPG; i++) {
            float v = al2s[i] + adj;
            v = (v > 0.f) ? v : 0.2f * v;
            e[i] = v; m = fmaxf(m, v);
        }
        float s = 0.f;
        #pragma unroll
        for (int i = 0; i < NPG; i++) { float w = __expf(e[i] - m); e[i] = w; s += w; }
        float inv = 1.f / (s + 1e-16f);
        #pragma unroll
        for (int i = 0; i < NPG; i++) alpha2[j * 24 + i] = e[i] * inv;
    }
    __syncthreads();

    // ---- aggregate2 + bias + elu -> o2 (23 x 48) ----
    for (int idx = tid; idx < NPG * 12; idx += 256) {
        int j = idx / 12, k4 = idx - (idx / 12) * 12;
        float4 acc = ld4(b2s + 4 * k4);
        const float* a = alpha2 + j * 24;
        #pragma unroll
        for (int i = 0; i < NPG; i++) {
            float av = a[i];
            float4 h = ld4(h2 + i * HID + 4 * k4);
            acc.x += av * h.x; acc.y += av * h.y;
            acc.z += av * h.z; acc.w += av * h.w;
        }
        acc.x = elu1(acc.x); acc.y = elu1(acc.y);
        acc.z = elu1(acc.z); acc.w = elu1(acc.w);
        *(float4*)(o2 + j * HID + 4 * k4) = acc;
    }
    __syncthreads();

    // ---- mean/max pooling over nodes -> g_frames ----
    if (tid < HID) {
        float s = 0.f, m = -1e30f;
        #pragma unroll
        for (int j = 0; j < NPG; j++) {
            float v = o2[j * HID + tid];
            s += v; m = fmaxf(m, v);
        }
        g_frames[g * FRAME + tid]       = s * (1.f / (float)NPG);
        g_frames[g * FRAME + HID + tid] = m;
    }
}

// ---------------------------------------------------------------------------
// Kernel 2: gi0 = frames @ Wih0^T + bih0 as a wide GEMM over all 1024 rows.
// 128 blocks x 192 threads, 8 frame rows per block.
// ---------------------------------------------------------------------------
#define GI0_GPB 8
__global__ void __launch_bounds__(192) gi0_kernel(const float* __restrict__ Wih0,
                                                  const float* __restrict__ bih0)
{
    extern __shared__ float smem[];
    float* W  = smem;                 // 192 x stride 100 = 19200
    float* xf = smem + G3 * 100;      // 8 x 96 = 768

    const int tid = threadIdx.x;
    const int b0  = blockIdx.x * GI0_GPB;

    for (int i4 = tid; i4 < G3 * 24; i4 += 192) {
        int r = i4 / 24, c4 = i4 - (i4 / 24) * 24;
        *(float4*)(W + r * 100 + 4 * c4) = ld4(Wih0 + r * 96 + 4 * c4);
    }
    for (int i4 = tid; i4 < GI0_GPB * 24; i4 += 192)
        ((float4*)xf)[i4] = ((const float4*)(g_frames + (size_t)b0 * FRAME))[i4];
    __syncthreads();

    const int r = tid;               // output row 0..191
    float acc[GI0_GPB];
    float bi = bih0[r];
    #pragma unroll
    for (int gg = 0; gg < GI0_GPB; gg++) acc[gg] = bi;
    const float4* wr = (const float4*)(W + r * 100);
    #pragma unroll
    for (int f4 = 0; f4 < 24; f4++) {
        float4 w = wr[f4];
        #pragma unroll
        for (int gg = 0; gg < GI0_GPB; gg++) {
            float4 xv = ld4(xf + gg * 96 + 4 * f4);
            acc[gg] += w.x * xv.x + w.y * xv.y + w.z * xv.z + w.w * xv.w;
        }
    }
    #pragma unroll
    for (int gg = 0; gg < GI0_GPB; gg++)
        g_gi0[(size_t)(b0 + gg) * G3 + r] = acc[gg];
}

// ---------------------------------------------------------------------------
// Kernel 3: 2-layer GRU recurrence + MLP head. One block per batch row.
// gi0 precomputed; gi1 batched over all 16 steps; 4-way split accumulators.
// ---------------------------------------------------------------------------
__global__ void __launch_bounds__(192) gru_kernel(
    const float* __restrict__ Whh0, const float* __restrict__ bhh0,
    const float* __restrict__ Wih1, const float* __restrict__ bih1,
    const float* __restrict__ Whh1, const float* __restrict__ bhh1,
    const float* __restrict__ Wh1,  const float* __restrict__ bh1,
    const float* __restrict__ Wh2,  const float* __restrict__ bh2,
    float* __restrict__ out)
{
    extern __shared__ float smem[];
    float* Wis  = smem;               // 192 x 68 = 13056 (Wih1)
    float* Whs  = Wis + G3 * 68;      // 192 x 68 = 13056 (Whh staging)
    float* gi   = Whs + G3 * 68;      // 16 x 192 = 3072
    float* seq  = gi  + TT * G3;      // 16 x 64 = 1024
    float* hbuf = seq + TT * GRUH;    // 64
    float* gh   = hbuf + GRUH;        // 192
    float* q    = gh + G3;            // 32

    const int b = blockIdx.x;
    const int tid = threadIdx.x;

    // gi0 for this batch row (16 x 192)
    for (int i4 = tid; i4 < TT * G3 / 4; i4 += 192)
        ((float4*)gi)[i4] = ((const float4*)(g_gi0 + (size_t)b * TT * G3))[i4];
    // Whh0 -> Whs (stride 68)
    for (int i4 = tid; i4 < G3 * 16; i4 += 192) {
        int r = i4 >> 4, c4 = i4 & 15;
        *(float4*)(Whs + r * 68 + 4 * c4) = ld4(Whh0 + r * 64 + 4 * c4);
    }
    if (tid < GRUH) hbuf[tid] = 0.f;
    __syncthreads();

    float wr[GRUH];
    #pragma unroll
    for (int c4 = 0; c4 < 16; c4++) {
        float4 v = ld4(Whs + tid * 68 + 4 * c4);
        wr[4 * c4] = v.x; wr[4 * c4 + 1] = v.y; wr[4 * c4 + 2] = v.z; wr[4 * c4 + 3] = v.w;
    }
    float bh = bhh0[tid];
    __syncthreads();

    // ---- layer 0 recurrence (writes seq) ----
    for (int t = 0; t < TT; t++) {
        float a0 = 0.f, a1 = 0.f, a2 = 0.f, a3 = 0.f;
        #pragma unroll
        for (int u4 = 0; u4 < 16; u4++) {
            float4 hv = ld4(hbuf + 4 * u4);
            a0 += wr[4 * u4]     * hv.x;
            a1 += wr[4 * u4 + 1] * hv.y;
            a2 += wr[4 * u4 + 2] * hv.z;
            a3 += wr[4 * u4 + 3] * hv.w;
        }
        gh[tid] = (a0 + a1) + (a2 + a3) + bh;
        __syncthreads();
        if (tid < GRUH) {
            float gir = gi[t * G3 + tid];
            float giz = gi[t * G3 + GRUH + tid];
            float gin = gi[t * G3 + 2 * GRUH + tid];
            float r = fast_sigmoid(gir + gh[tid]);
            float z = fast_sigmoid(giz + gh[GRUH + tid]);
            float n = fast_tanh(gin + r * gh[2 * GRUH + tid]);
            float hn = (1.f - z) * n + z * hbuf[tid];
            hbuf[tid] = hn;
            seq[t * GRUH + tid] = hn;
        }
        __syncthreads();
    }

    // ---- load layer-1 weights ----
    for (int i4 = tid; i4 < G3 * 16; i4 += 192) {
        int r = i4 >> 4, c4 = i4 & 15;
        *(float4*)(Wis + r * 68 + 4 * c4) = ld4(Wih1 + r * 64 + 4 * c4);
        *(float4*)(Whs + r * 68 + 4 * c4) = ld4(Whh1 + r * 64 + 4 * c4);
    }
    __syncthreads();

    // ---- gi1 for all 16 steps ----
    {
        float acc[TT];
        float bi = bih1[tid];
        #pragma unroll
        for (int t = 0; t < TT; t++) acc[t] = bi;
        const float4* wrow = (const float4*)(Wis + tid * 68);
        #pragma unroll
        for (int f4 = 0; f4 < 16; f4++) {
            float4 w = wrow[f4];
            #pragma unroll
            for (int t = 0; t < TT; t++) {
                float4 xv = ld4(seq + t * GRUH + 4 * f4);
                acc[t] += w.x * xv.x + w.y * xv.y + w.z * xv.z + w.w * xv.w;
            }
        }
        #pragma unroll
        for (int t = 0; t < TT; t++) gi[t * G3 + tid] = acc[t];
    }

    #pragma unroll
    for (int c4 = 0; c4 < 16; c4++) {
        float4 v = ld4(Whs + tid * 68 + 4 * c4);
        wr[4 * c4] = v.x; wr[4 * c4 + 1] = v.y; wr[4 * c4 + 2] = v.z; wr[4 * c4 + 3] = v.w;
    }
    bh = bhh1[tid];
    if (tid < GRUH) hbuf[tid] = 0.f;
    __syncthreads();

    // ---- layer 1 recurrence (only final h needed) ----
    for (int t = 0; t < TT; t++) {
        float a0 = 0.f, a1 = 0.f, a2 = 0.f, a3 = 0.f;
        #pragma unroll
        for (int u4 = 0; u4 < 16; u4++) {
            float4 hv = ld4(hbuf + 4 * u4);
            a0 += wr[4 * u4]     * hv.x;
            a1 += wr[4 * u4 + 1] * hv.y;
            a2 += wr[4 * u4 + 2] * hv.z;
            a3 += wr[4 * u4 + 3] * hv.w;
        }
        gh[tid] = (a0 + a1) + (a2 + a3) + bh;
        __syncthreads();
        if (tid < GRUH) {
            float gir = gi[t * G3 + tid];
            float giz = gi[t * G3 + GRUH + tid];
            float gin = gi[t * G3 + 2 * GRUH + tid];
            float r = fast_sigmoid(gir + gh[tid]);
            float z = fast_sigmoid(giz + gh[GRUH + tid]);
            float n = fast_tanh(gin + r * gh[2 * GRUH + tid]);
            hbuf[tid] = (1.f - z) * n + z * hbuf[tid];
        }
        __syncthreads();
    }

    // ---- MLP head ----
    if (tid < 32) {
        float acc = bh1[tid];
        #pragma unroll
        for (int u = 0; u < GRUH; u++) acc += hbuf[u] * Wh1[u * 32 + tid];
        q[tid] = fmaxf(acc, 0.f);
    }
    __syncthreads();
    if (tid == 0) {
        float acc = bh2[0];
        #pragma unroll
        for (int m = 0; m < 32; m++) acc += q[m] * Wh2[m];
        out[b] = acc;
    }
}

// ---------------------------------------------------------------------------
extern "C" void kernel_launch(void* const* d_in, const int* in_sizes, int n_in,
                              void* d_out, int out_size)
{
    const float* x    = (const float*)d_in[0];
    // d_in[1]=edge_index, d_in[2]=batch : fixed dense structure, unused
    const float* W1   = (const float*)d_in[3];
    const float* as1  = (const float*)d_in[4];
    const float* ad1  = (const float*)d_in[5];
    const float* b1   = (const float*)d_in[6];
    const float* W2   = (const float*)d_in[7];
    const float* as2  = (const float*)d_in[8];
    const float* ad2  = (const float*)d_in[9];
    const float* b2   = (const float*)d_in[10];
    const float* Wih0 = (const float*)d_in[11];
    const float* Whh0 = (const float*)d_in[12];
    const float* bih0 = (const float*)d_in[13];
    const float* bhh0 = (const float*)d_in[14];
    const float* Wih1 = (const float*)d_in[15];
    const float* Whh1 = (const float*)d_in[16];
    const float* bih1 = (const float*)d_in[17];
    const float* bhh1 = (const float*)d_in[18];
    const float* Wh1  = (const float*)d_in[19];
    const float* bh1  = (const float*)d_in[20];
    const float* Wh2  = (const float*)d_in[21];
    const float* bh2  = (const float*)d_in[22];

    const int GAT_SMEM = 26456 * 4;                 // 105824
    const int GI0_SMEM = (G3 * 100 + GI0_GPB * FRAME) * 4;   // 79872
    const int GRU_SMEM = (2 * G3 * 68 + TT * G3 + TT * GRUH + GRUH + G3 + 32) * 4;

    static bool attrs_set = false;
    if (!attrs_set) {
        cudaFuncSetAttribute(gat_kernel, cudaFuncAttributeMaxDynamicSharedMemorySize, GAT_SMEM);
        cudaFuncSetAttribute(gi0_kernel, cudaFuncAttributeMaxDynamicSharedMemorySize, GI0_SMEM);
        cudaFuncSetAttribute(gru_kernel, cudaFuncAttributeMaxDynamicSharedMemorySize, GRU_SMEM);
        attrs_set = true;
    }

    gat_kernel<<<NGRAPH, 256, GAT_SMEM>>>(x, W1, as1, ad1, b1, W2, as2, ad2, b2);
    gi0_kernel<<<NGRAPH / GI0_GPB, 192, GI0_SMEM>>>(Wih0, bih0);
    gru_kernel<<<BB, 192, GRU_SMEM>>>(Whh0, bhh0, Wih1, bih1, Whh1, bhh1,
                                      Wh1, bh1, Wh2, bh2, (float*)d_out);
}

// round 3
// speedup vs baseline: 1.6788x; 1.3093x over previous
#include <cuda_runtime.h>

#define NPG 23
#define NF 11
#define HID 48
#define C1 192
#define NGRAPH 1024
#define GRUH 64
#define G3 192
#define TT 16
#define BB 64
#define FRAME 96
#define ST 196           // padded float4-aligned stride for 192-wide rows

__device__ float g_frames[NGRAPH * FRAME];
__device__ float g_gi0[NGRAPH * G3];

__device__ __forceinline__ float4 ld4(const float* p) { return *(const float4*)p; }

__device__ __forceinline__ float fast_sigmoid(float x) {
    return 1.f / (1.f + __expf(-x));
}
__device__ __forceinline__ float fast_tanh(float x) {
    float e = __expf(-2.f * x);
    return (1.f - e) / (1.f + e);
}
__device__ __forceinline__ float elu1(float v) {
    return v > 0.f ? v : (__expf(v) - 1.f);
}

// ---------------------------------------------------------------------------
// Kernel 1: fused GAT1 + GAT2 + pooling. One block per 23-node group.
// All GEMM-ish loops 2-D register tiled: each smem weight float4 feeds
// 4-5 rows of output (>=0.5 MAC/byte -> smem crossbar no longer the bound).
// ---------------------------------------------------------------------------
__global__ void __launch_bounds__(256) gat_kernel(
    const float* __restrict__ x,
    const float* __restrict__ W1,  const float* __restrict__ as1,
    const float* __restrict__ ad1, const float* __restrict__ b1,
    const float* __restrict__ W2,  const float* __restrict__ as2,
    const float* __restrict__ ad2, const float* __restrict__ b2)
{
    extern __shared__ float sm[];
    float* W1s    = sm;             // 2112   (float4 layout [f][c4])
    float* W2s    = W1s  + 2112;    // 9216   (float4 layout [c][k4])
    float* a1s    = W2s  + 9216;    // 192
    float* a1d    = a1s  + 192;     // 192
    float* b1s    = a1d  + 192;     // 192
    float* a2s    = b1s  + 192;     // 48
    float* a2d    = a2s  + 48;      // 48
    float* b2s    = a2d  + 48;      // 48
    float* xs     = b2s  + 48;      // 276 (23 x stride 12)
    float* h1     = xs   + 276;     // 23*196 = 4508 ; reused as h2 partials (4416)
    float* o1     = h1   + 4508;    // 4508
    float* als    = o1   + 4508;    // 96
    float* ald    = als  + 96;      // 96
    float* alpha  = ald  + 96;      // 4*23*23 = 2116
    float* h2     = alpha+ 2116;    // 23*48 = 1104
    float* al2s   = h2   + 1104;    // 24
    float* al2d   = al2s + 24;      // 24
    float* alpha2 = al2d + 24;      // 23*24 = 552
    float* o2     = alpha2 + 552;   // 1104
    // total 26456 floats = 105824 B

    const int tid = threadIdx.x;
    const int g   = blockIdx.x;

    // ---- cooperative loads (vectorized) ----
    for (int i4 = tid; i4 < 2112 / 4; i4 += 256)
        ((float4*)W1s)[i4] = ((const float4*)W1)[i4];
    for (int i4 = tid; i4 < 9216 / 4; i4 += 256)
        ((float4*)W2s)[i4] = ((const float4*)W2)[i4];
    if (tid < 192) { a1s[tid] = as1[tid]; a1d[tid] = ad1[tid]; b1s[tid] = b1[tid]; }
    else if (tid < 240) {
        int k = tid - 192;
        a2s[k] = as2[k]; a2d[k] = ad2[k]; b2s[k] = b2[k];
    }
    const float* xg = x + (size_t)g * (NPG * NF);
    for (int i = tid; i < NPG * NF; i += 256) {
        int r = i / NF, c = i - r * NF;
        xs[r * 12 + c] = xg[i];
    }
    __syncthreads();

    // ---- h1 = x @ W1  (23 x 192): 48 colgroups x 5-row tiles (240 threads) ----
    if (tid < 240) {
        int c4 = tid % 48, rg = tid / 48;
        int r0 = rg * 5;
        int nr = (r0 + 5 <= NPG) ? 5 : (NPG - r0);
        float4 acc[5];
        #pragma unroll
        for (int rr = 0; rr < 5; rr++) acc[rr] = make_float4(0.f, 0.f, 0.f, 0.f);
        #pragma unroll
        for (int f = 0; f < NF; f++) {
            float4 w = ((const float4*)W1s)[f * 48 + c4];
            #pragma unroll
            for (int rr = 0; rr < 5; rr++) {
                if (rr < nr) {
                    float xv = xs[(r0 + rr) * 12 + f];
                    acc[rr].x += xv * w.x; acc[rr].y += xv * w.y;
                    acc[rr].z += xv * w.z; acc[rr].w += xv * w.w;
                }
            }
        }
        #pragma unroll
        for (int rr = 0; rr < 5; rr++)
            if (rr < nr) *(float4*)(h1 + (r0 + rr) * ST + 4 * c4) = acc[rr];
    }
    __syncthreads();

    // ---- attention logits per (node, head) ----
    if (tid < NPG * 4) {
        int i = tid >> 2, hd = tid & 3;
        const float* hrow = h1 + i * ST + hd * HID;
        const float* sv = a1s + hd * HID;
        const float* dv = a1d + hd * HID;
        float ss = 0.f, dd = 0.f;
        #pragma unroll
        for (int k4 = 0; k4 < 12; k4++) {
            float4 v = ld4(hrow + 4 * k4);
            float4 s4 = ld4(sv + 4 * k4);
            float4 d4 = ld4(dv + 4 * k4);
            ss += v.x * s4.x + v.y * s4.y + v.z * s4.z + v.w * s4.w;
            dd += v.x * d4.x + v.y * d4.y + v.z * d4.z + v.w * d4.w;
        }
        als[tid] = ss; ald[tid] = dd;
    }
    __syncthreads();

    // ---- softmax over sources for each (dst j, head) ----
    if (tid < NPG * 4) {
        int j = tid >> 2, hd = tid & 3;
        float adj = ald[j * 4 + hd];
        float e[NPG];
        float m = -1e30f;
        #pragma unroll
        for (int i = 0; i < NPG; i++) {
            float v = als[i * 4 + hd] + adj;
            v = (v > 0.f) ? v : 0.2f * v;
            e[i] = v; m = fmaxf(m, v);
        }
        float s = 0.f;
        #pragma unroll
        for (int i = 0; i < NPG; i++) { float w = __expf(e[i] - m); e[i] = w; s += w; }
        float inv = 1.f / (s + 1e-16f);
        #pragma unroll
        for (int i = 0; i < NPG; i++) alpha[(hd * NPG + j) * NPG + i] = e[i] * inv;
    }
    __syncthreads();

    // ---- aggregate1 + bias + elu -> o1: 48 colgroups x 5-dst-row tiles ----
    if (tid < 240) {
        int c4 = tid % 48, rg = tid / 48;
        int j0 = rg * 5;
        int nj = (j0 + 5 <= NPG) ? 5 : (NPG - j0);
        int hd = c4 / 12;
        float4 bv = ld4(b1s + 4 * c4);
        float4 acc[5];
        #pragma unroll
        for (int jj = 0; jj < 5; jj++) acc[jj] = bv;
        const float* arow = alpha + (hd * NPG + j0) * NPG;
        #pragma unroll
        for (int i = 0; i < NPG; i++) {
            float4 h = ld4(h1 + i * ST + 4 * c4);
            #pragma unroll
            for (int jj = 0; jj < 5; jj++) {
                if (jj < nj) {
                    float av = arow[jj * NPG + i];
                    acc[jj].x += av * h.x; acc[jj].y += av * h.y;
                    acc[jj].z += av * h.z; acc[jj].w += av * h.w;
                }
            }
        }
        #pragma unroll
        for (int jj = 0; jj < 5; jj++) {
            if (jj < nj) {
                float4 a = acc[jj];
                a.x = elu1(a.x); a.y = elu1(a.y); a.z = elu1(a.z); a.w = elu1(a.w);
                *(float4*)(o1 + (j0 + jj) * ST + 4 * c4) = a;
            }
        }
    }
    __syncthreads();

    // ---- h2 = o1 @ W2 (23 x 48): K-split-4 x 4-row x 4-col tiles ----
    // 288 tasks: partials into the (now dead) h1 buffer, then combine.
    {
        float* part = h1;                       // [ks][row][col] : 4*23*48 = 4416
        for (int idx = tid; idx < 288; idx += 256) {
            int ks = idx / 72;
            int rem = idx - ks * 72;
            int k4 = rem % 12, rg = rem / 12;
            int r0 = rg * 4;
            int nr = (r0 + 4 <= NPG) ? 4 : (NPG - r0);
            int c0 = ks * 48;
            float4 acc[4];
            #pragma unroll
            for (int rr = 0; rr < 4; rr++) acc[rr] = make_float4(0.f, 0.f, 0.f, 0.f);
            #pragma unroll 8
            for (int c = c0; c < c0 + 48; c++) {
                float4 w = ((const float4*)W2s)[c * 12 + k4];
                #pragma unroll
                for (int rr = 0; rr < 4; rr++) {
                    if (rr < nr) {
                        float ov = o1[(r0 + rr) * ST + c];
                        acc[rr].x += ov * w.x; acc[rr].y += ov * w.y;
                        acc[rr].z += ov * w.z; acc[rr].w += ov * w.w;
                    }
                }
            }
            #pragma unroll
            for (int rr = 0; rr < 4; rr++)
                if (rr < nr)
                    *(float4*)(part + ks * 1104 + (r0 + rr) * 48 + 4 * k4) = acc[rr];
        }
        __syncthreads();
        // combine 4 K-partials (deterministic order)
        for (int i4 = tid; i4 < 276; i4 += 256) {
            float4 p0 = ((const float4*)part)[i4];
            float4 p1 = ((const float4*)(part + 1104))[i4];
            float4 p2 = ((const float4*)(part + 2208))[i4];
            float4 p3 = ((const float4*)(part + 3312))[i4];
            float4 s;
            s.x = (p0.x + p1.x) + (p2.x + p3.x);
            s.y = (p0.y + p1.y) + (p2.y + p3.y);
            s.z = (p0.z + p1.z) + (p2.z + p3.z);
            s.w = (p0.w + p1.w) + (p2.w + p3.w);
            ((float4*)h2)[i4] = s;
        }
    }
    __syncthreads();

    // ---- GAT2 logits ----
    if (tid < NPG) {
        const float* hrow = h2 + tid * HID;
        float ss = 0.f, dd = 0.f;
        #pragma unroll
        for (int k4 = 0; k4 < 12; k4++) {
            float4 v = ld4(hrow + 4 * k4);
            float4 s4 = ld4(a2s + 4 * k4);
            float4 d4 = ld4(a2d + 4 * k4);
            ss += v.x * s4.x + v.y * s4.y + v.z * s4.z + v.w * s4.w;
            dd += v.x * d4.x + v.y * d4.y + v.z * d4.z + v.w * d4.w;
        }
        al2s[tid] = ss; al2d[tid] = dd;
    }
    __syncthreads();

    if (tid < NPG) {
        int j = tid;
        float adj = al2d[j];
        float e[NPG];
        float m = -1e30f;
        #pragma unroll
        for (int i = 0; i < NPG; i++) {
            float v = al2s[i] + adj;
            v = (v > 0.f) ? v : 0.2f * v;
            e[i] = v; m = fmaxf(m, v);
        }
        float s = 0.f;
        #pragma unroll
        for (int i = 0; i < NPG; i++) { float w = __expf(e[i] - m); e[i] = w; s += w; }
        float inv = 1.f / (s + 1e-16f);
        #pragma unroll
        for (int i = 0; i < NPG; i++) alpha2[j * 24 + i] = e[i] * inv;
    }
    __syncthreads();

    // ---- aggregate2 + bias + elu -> o2: 12 colgroups x 4-row tiles (72 tasks) ----
    if (tid < 72) {
        int k4 = tid % 12, rg = tid / 12;
        int j0 = rg * 4;
        int nj = (j0 + 4 <= NPG) ? 4 : (NPG - j0);
        float4 bv = ld4(b2s + 4 * k4);
        float4 acc[4];
        #pragma unroll
        for (int jj = 0; jj < 4; jj++) acc[jj] = bv;
        #pragma unroll
        for (int i = 0; i < NPG; i++) {
            float4 h = ld4(h2 + i * HID + 4 * k4);
            #pragma unroll
            for (int jj = 0; jj < 4; jj++) {
                if (jj < nj) {
                    float av = alpha2[(j0 + jj) * 24 + i];
                    acc[jj].x += av * h.x; acc[jj].y += av * h.y;
                    acc[jj].z += av * h.z; acc[jj].w += av * h.w;
                }
            }
        }
        #pragma unroll
        for (int jj = 0; jj < 4; jj++) {
            if (jj < nj) {
                float4 a = acc[jj];
                a.x = elu1(a.x); a.y = elu1(a.y); a.z = elu1(a.z); a.w = elu1(a.w);
                *(float4*)(o2 + (j0 + jj) * HID + 4 * k4) = a;
            }
        }
    }
    __syncthreads();

    // ---- mean/max pooling over nodes -> g_frames ----
    if (tid < HID) {
        float s = 0.f, m = -1e30f;
        #pragma unroll
        for (int j = 0; j < NPG; j++) {
            float v = o2[j * HID + tid];
            s += v; m = fmaxf(m, v);
        }
        g_frames[g * FRAME + tid]       = s * (1.f / (float)NPG);
        g_frames[g * FRAME + HID + tid] = m;
    }
}

// ---------------------------------------------------------------------------
// Kernel 2: gi0 = frames @ Wih0^T + bih0 as a wide GEMM over all 1024 rows.
// ---------------------------------------------------------------------------
#define GI0_GPB 8
__global__ void __launch_bounds__(192) gi0_kernel(const float* __restrict__ Wih0,
                                                  const float* __restrict__ bih0)
{
    extern __shared__ float smem[];
    float* W  = smem;                 // 192 x stride 100 = 19200
    float* xf = smem + G3 * 100;      // 8 x 96 = 768

    const int tid = threadIdx.x;
    const int b0  = blockIdx.x * GI0_GPB;

    for (int i4 = tid; i4 < G3 * 24; i4 += 192) {
        int r = i4 / 24, c4 = i4 - (i4 / 24) * 24;
        *(float4*)(W + r * 100 + 4 * c4) = ld4(Wih0 + r * 96 + 4 * c4);
    }
    for (int i4 = tid; i4 < GI0_GPB * 24; i4 += 192)
        ((float4*)xf)[i4] = ((const float4*)(g_frames + (size_t)b0 * FRAME))[i4];
    __syncthreads();

    const int r = tid;
    float acc[GI0_GPB];
    float bi = bih0[r];
    #pragma unroll
    for (int gg = 0; gg < GI0_GPB; gg++) acc[gg] = bi;
    const float4* wr = (const float4*)(W + r * 100);
    #pragma unroll
    for (int f4 = 0; f4 < 24; f4++) {
        float4 w = wr[f4];
        #pragma unroll
        for (int gg = 0; gg < GI0_GPB; gg++) {
            float4 xv = ld4(xf + gg * 96 + 4 * f4);
            acc[gg] += w.x * xv.x + w.y * xv.y + w.z * xv.z + w.w * xv.w;
        }
    }
    #pragma unroll
    for (int gg = 0; gg < GI0_GPB; gg++)
        g_gi0[(size_t)(b0 + gg) * G3 + r] = acc[gg];
}

// ---------------------------------------------------------------------------
// Kernel 3: 2-layer GRU recurrence + MLP head. One block per batch row.
// ---------------------------------------------------------------------------
__global__ void __launch_bounds__(192) gru_kernel(
    const float* __restrict__ Whh0, const float* __restrict__ bhh0,
    const float* __restrict__ Wih1, const float* __restrict__ bih1,
    const float* __restrict__ Whh1, const float* __restrict__ bhh1,
    const float* __restrict__ Wh1,  const float* __restrict__ bh1,
    const float* __restrict__ Wh2,  const float* __restrict__ bh2,
    float* __restrict__ out)
{
    extern __shared__ float smem[];
    float* Wis  = smem;               // 192 x 68
    float* Whs  = Wis + G3 * 68;      // 192 x 68
    float* gi   = Whs + G3 * 68;      // 16 x 192
    float* seq  = gi  + TT * G3;      // 16 x 64
    float* hbuf = seq + TT * GRUH;    // 64
    float* gh   = hbuf + GRUH;        // 192
    float* q    = gh + G3;            // 32

    const int b = blockIdx.x;
    const int tid = threadIdx.x;

    for (int i4 = tid; i4 < TT * G3 / 4; i4 += 192)
        ((float4*)gi)[i4] = ((const float4*)(g_gi0 + (size_t)b * TT * G3))[i4];
    for (int i4 = tid; i4 < G3 * 16; i4 += 192) {
        int r = i4 >> 4, c4 = i4 & 15;
        *(float4*)(Whs + r * 68 + 4 * c4) = ld4(Whh0 + r * 64 + 4 * c4);
    }
    if (tid < GRUH) hbuf[tid] = 0.f;
    __syncthreads();

    float wr[GRUH];
    #pragma unroll
    for (int c4 = 0; c4 < 16; c4++) {
        float4 v = ld4(Whs + tid * 68 + 4 * c4);
        wr[4 * c4] = v.x; wr[4 * c4 + 1] = v.y; wr[4 * c4 + 2] = v.z; wr[4 * c4 + 3] = v.w;
    }
    float bh = bhh0[tid];
    __syncthreads();

    for (int t = 0; t < TT; t++) {
        float a0 = 0.f, a1 = 0.f, a2 = 0.f, a3 = 0.f;
        #pragma unroll
        for (int u4 = 0; u4 < 16; u4++) {
            float4 hv = ld4(hbuf + 4 * u4);
            a0 += wr[4 * u4]     * hv.x;
            a1 += wr[4 * u4 + 1] * hv.y;
            a2 += wr[4 * u4 + 2] * hv.z;
            a3 += wr[4 * u4 + 3] * hv.w;
        }
        gh[tid] = (a0 + a1) + (a2 + a3) + bh;
        __syncthreads();
        if (tid < GRUH) {
            float gir = gi[t * G3 + tid];
            float giz = gi[t * G3 + GRUH + tid];
            float gin = gi[t * G3 + 2 * GRUH + tid];
            float r = fast_sigmoid(gir + gh[tid]);
            float z = fast_sigmoid(giz + gh[GRUH + tid]);
            float n = fast_tanh(gin + r * gh[2 * GRUH + tid]);
            float hn = (1.f - z) * n + z * hbuf[tid];
            hbuf[tid] = hn;
            seq[t * GRUH + tid] = hn;
        }
        __syncthreads();
    }

    for (int i4 = tid; i4 < G3 * 16; i4 += 192) {
        int r = i4 >> 4, c4 = i4 & 15;
        *(float4*)(Wis + r * 68 + 4 * c4) = ld4(Wih1 + r * 64 + 4 * c4);
        *(float4*)(Whs + r * 68 + 4 * c4) = ld4(Whh1 + r * 64 + 4 * c4);
    }
    __syncthreads();

    {
        float acc[TT];
        float bi = bih1[tid];
        #pragma unroll
        for (int t = 0; t < TT; t++) acc[t] = bi;
        const float4* wrow = (const float4*)(Wis + tid * 68);
        #pragma unroll
        for (int f4 = 0; f4 < 16; f4++) {
            float4 w = wrow[f4];
            #pragma unroll
            for (int t = 0; t < TT; t++) {
                float4 xv = ld4(seq + t * GRUH + 4 * f4);
                acc[t] += w.x * xv.x + w.y * xv.y + w.z * xv.z + w.w * xv.w;
            }
        }
        #pragma unroll
        for (int t = 0; t < TT; t++) gi[t * G3 + tid] = acc[t];
    }

    #pragma unroll
    for (int c4 = 0; c4 < 16; c4++) {
        float4 v = ld4(Whs + tid * 68 + 4 * c4);
        wr[4 * c4] = v.x; wr[4 * c4 + 1] = v.y; wr[4 * c4 + 2] = v.z; wr[4 * c4 + 3] = v.w;
    }
    bh = bhh1[tid];
    if (tid < GRUH) hbuf[tid] = 0.f;
    __syncthreads();

    for (int t = 0; t < TT; t++) {
        float a0 = 0.f, a1 = 0.f, a2 = 0.f, a3 = 0.f;
        #pragma unroll
        for (int u4 = 0; u4 < 16; u4++) {
            float4 hv = ld4(hbuf + 4 * u4);
            a0 += wr[4 * u4]     * hv.x;
            a1 += wr[4 * u4 + 1] * hv.y;
            a2 += wr[4 * u4 + 2] * hv.z;
            a3 += wr[4 * u4 + 3] * hv.w;
        }
        gh[tid] = (a0 + a1) + (a2 + a3) + bh;
        __syncthreads();
        if (tid < GRUH) {
            float gir = gi[t * G3 + tid];
            float giz = gi[t * G3 + GRUH + tid];
            float gin = gi[t * G3 + 2 * GRUH + tid];
            float r = fast_sigmoid(gir + gh[tid]);
            float z = fast_sigmoid(giz + gh[GRUH + tid]);
            float n = fast_tanh(gin + r * gh[2 * GRUH + tid]);
            hbuf[tid] = (1.f - z) * n + z * hbuf[tid];
        }
        __syncthreads();
    }

    if (tid < 32) {
        float acc = bh1[tid];
        #pragma unroll
        for (int u = 0; u < GRUH; u++) acc += hbuf[u] * Wh1[u * 32 + tid];
        q[tid] = fmaxf(acc, 0.f);
    }
    __syncthreads();
    if (tid == 0) {
        float acc = bh2[0];
        #pragma unroll
        for (int m = 0; m < 32; m++) acc += q[m] * Wh2[m];
        out[b] = acc;
    }
}

// ---------------------------------------------------------------------------
extern "C" void kernel_launch(void* const* d_in, const int* in_sizes, int n_in,
                              void* d_out, int out_size)
{
    const float* x    = (const float*)d_in[0];
    const float* W1   = (const float*)d_in[3];
    const float* as1  = (const float*)d_in[4];
    const float* ad1  = (const float*)d_in[5];
    const float* b1   = (const float*)d_in[6];
    const float* W2   = (const float*)d_in[7];
    const float* as2  = (const float*)d_in[8];
    const float* ad2  = (const float*)d_in[9];
    const float* b2   = (const float*)d_in[10];
    const float* Wih0 = (const float*)d_in[11];
    const float* Whh0 = (const float*)d_in[12];
    const float* bih0 = (const float*)d_in[13];
    const float* bhh0 = (const float*)d_in[14];
    const float* Wih1 = (const float*)d_in[15];
    const float* Whh1 = (const float*)d_in[16];
    const float* bih1 = (const float*)d_in[17];
    const float* bhh1 = (const float*)d_in[18];
    const float* Wh1  = (const float*)d_in[19];
    const float* bh1  = (const float*)d_in[20];
    const float* Wh2  = (const float*)d_in[21];
    const float* bh2  = (const float*)d_in[22];

    const int GAT_SMEM = 26456 * 4;
    const int GI0_SMEM = (G3 * 100 + GI0_GPB * FRAME) * 4;
    const int GRU_SMEM = (2 * G3 * 68 + TT * G3 + TT * GRUH + GRUH + G3 + 32) * 4;

    static bool attrs_set = false;
    if (!attrs_set) {
        cudaFuncSetAttribute(gat_kernel, cudaFuncAttributeMaxDynamicSharedMemorySize, GAT_SMEM);
        cudaFuncSetAttribute(gi0_kernel, cudaFuncAttributeMaxDynamicSharedMemorySize, GI0_SMEM);
        cudaFuncSetAttribute(gru_kernel, cudaFuncAttributeMaxDynamicSharedMemorySize, GRU_SMEM);
        attrs_set = true;
    }

    gat_kernel<<<NGRAPH, 256, GAT_SMEM>>>(x, W1, as1, ad1, b1, W2, as2, ad2, b2);
    gi0_kernel<<<NGRAPH / GI0_GPB, 192, GI0_SMEM>>>(Wih0, bih0);
    gru_kernel<<<BB, 192, GRU_SMEM>>>(Whh0, bhh0, Wih1, bih1, Whh1, bhh1,
                                      Wh1, bh1, Wh2, bh2, (float*)d_out);
}

// round 4
// speedup vs baseline: 1.9592x; 1.1670x over previous
#include <cuda_runtime.h>

#define NPG 23
#define NF 11
#define HID 48
#define C1 192
#define NGRAPH 1024
#define GRUH 64
#define G3 192
#define TT 16
#define BB 64
#define FRAME 96
#define ST 196           // padded float4-aligned stride for 192-wide rows

__device__ float g_frames[NGRAPH * FRAME];
__device__ float g_gi0[NGRAPH * G3];

__device__ __forceinline__ float4 ld4(const float* p) { return *(const float4*)p; }

__device__ __forceinline__ float fast_sigmoid(float x) {
    return 1.f / (1.f + __expf(-x));
}
__device__ __forceinline__ float fast_tanh(float x) {
    float e = __expf(-2.f * x);
    return (1.f - e) / (1.f + e);
}
__device__ __forceinline__ float elu1(float v) {
    return v > 0.f ? v : (__expf(v) - 1.f);
}

// ---------------------------------------------------------------------------
// Kernel 1: fused GAT1 + GAT2 + pooling. One block per 23-node group.
// W2 is NOT staged in smem: the h2 phase streams it from L2 (__ldg, identical
// across all 1024 blocks -> pure L2 broadcast). Smem 69KB -> 3 blocks/SM.
// ---------------------------------------------------------------------------
__global__ void __launch_bounds__(256) gat_kernel(
    const float* __restrict__ x,
    const float* __restrict__ W1,  const float* __restrict__ as1,
    const float* __restrict__ ad1, const float* __restrict__ b1,
    const float* __restrict__ W2,  const float* __restrict__ as2,
    const float* __restrict__ ad2, const float* __restrict__ b2)
{
    extern __shared__ float sm[];
    float* W1s    = sm;             // 2112   (float4 layout [f][c4])
    float* a1s    = W1s  + 2112;    // 192
    float* a1d    = a1s  + 192;     // 192
    float* b1s    = a1d  + 192;     // 192
    float* a2s    = b1s  + 192;     // 48
    float* a2d    = a2s  + 48;      // 48
    float* b2s    = a2d  + 48;      // 48
    float* xs     = b2s  + 48;      // 276 (23 x stride 12)
    float* h1     = xs   + 276;     // 23*196 = 4508 ; reused as h2 partials (4416)
    float* o1     = h1   + 4508;    // 4508
    float* als    = o1   + 4508;    // 96
    float* ald    = als  + 96;      // 96
    float* alpha  = ald  + 96;      // 4*23*23 = 2116
    float* h2     = alpha+ 2116;    // 23*48 = 1104
    float* al2s   = h2   + 1104;    // 24
    float* al2d   = al2s + 24;      // 24
    float* alpha2 = al2d + 24;      // 23*24 = 552
    float* o2     = alpha2 + 552;   // 1104
    // total 17240 floats = 68960 B

    const int tid = threadIdx.x;
    const int g   = blockIdx.x;

    // ---- cooperative loads (vectorized) ----
    for (int i4 = tid; i4 < 2112 / 4; i4 += 256)
        ((float4*)W1s)[i4] = ((const float4*)W1)[i4];
    if (tid < 192) { a1s[tid] = as1[tid]; a1d[tid] = ad1[tid]; b1s[tid] = b1[tid]; }
    else if (tid < 240) {
        int k = tid - 192;
        a2s[k] = as2[k]; a2d[k] = ad2[k]; b2s[k] = b2[k];
    }
    const float* xg = x + (size_t)g * (NPG * NF);
    for (int i = tid; i < NPG * NF; i += 256) {
        int r = i / NF, c = i - r * NF;
        xs[r * 12 + c] = xg[i];
    }
    __syncthreads();

    // ---- h1 = x @ W1  (23 x 192): 48 colgroups x 5-row tiles (240 threads) ----
    if (tid < 240) {
        int c4 = tid % 48, rg = tid / 48;
        int r0 = rg * 5;
        int nr = (r0 + 5 <= NPG) ? 5 : (NPG - r0);
        float4 acc[5];
        #pragma unroll
        for (int rr = 0; rr < 5; rr++) acc[rr] = make_float4(0.f, 0.f, 0.f, 0.f);
        #pragma unroll
        for (int f = 0; f < NF; f++) {
            float4 w = ((const float4*)W1s)[f * 48 + c4];
            #pragma unroll
            for (int rr = 0; rr < 5; rr++) {
                if (rr < nr) {
                    float xv = xs[(r0 + rr) * 12 + f];
                    acc[rr].x += xv * w.x; acc[rr].y += xv * w.y;
                    acc[rr].z += xv * w.z; acc[rr].w += xv * w.w;
                }
            }
        }
        #pragma unroll
        for (int rr = 0; rr < 5; rr++)
            if (rr < nr) *(float4*)(h1 + (r0 + rr) * ST + 4 * c4) = acc[rr];
    }
    __syncthreads();

    // ---- attention logits per (node, head) ----
    if (tid < NPG * 4) {
        int i = tid >> 2, hd = tid & 3;
        const float* hrow = h1 + i * ST + hd * HID;
        const float* sv = a1s + hd * HID;
        const float* dv = a1d + hd * HID;
        float ss = 0.f, dd = 0.f;
        #pragma unroll
        for (int k4 = 0; k4 < 12; k4++) {
            float4 v = ld4(hrow + 4 * k4);
            float4 s4 = ld4(sv + 4 * k4);
            float4 d4 = ld4(dv + 4 * k4);
            ss += v.x * s4.x + v.y * s4.y + v.z * s4.z + v.w * s4.w;
            dd += v.x * d4.x + v.y * d4.y + v.z * d4.z + v.w * d4.w;
        }
        als[tid] = ss; ald[tid] = dd;
    }
    __syncthreads();

    // ---- softmax over sources for each (dst j, head) ----
    if (tid < NPG * 4) {
        int j = tid >> 2, hd = tid & 3;
        float adj = ald[j * 4 + hd];
        float e[NPG];
        float m = -1e30f;
        #pragma unroll
        for (int i = 0; i < NPG; i++) {
            float v = als[i * 4 + hd] + adj;
            v = (v > 0.f) ? v : 0.2f * v;
            e[i] = v; m = fmaxf(m, v);
        }
        float s = 0.f;
        #pragma unroll
        for (int i = 0; i < NPG; i++) { float w = __expf(e[i] - m); e[i] = w; s += w; }
        float inv = 1.f / (s + 1e-16f);
        #pragma unroll
        for (int i = 0; i < NPG; i++) alpha[(hd * NPG + j) * NPG + i] = e[i] * inv;
    }
    __syncthreads();

    // ---- aggregate1 + bias + elu -> o1: 48 colgroups x 5-dst-row tiles ----
    if (tid < 240) {
        int c4 = tid % 48, rg = tid / 48;
        int j0 = rg * 5;
        int nj = (j0 + 5 <= NPG) ? 5 : (NPG - j0);
        int hd = c4 / 12;
        float4 bv = ld4(b1s + 4 * c4);
        float4 acc[5];
        #pragma unroll
        for (int jj = 0; jj < 5; jj++) acc[jj] = bv;
        const float* arow = alpha + (hd * NPG + j0) * NPG;
        #pragma unroll
        for (int i = 0; i < NPG; i++) {
            float4 h = ld4(h1 + i * ST + 4 * c4);
            #pragma unroll
            for (int jj = 0; jj < 5; jj++) {
                if (jj < nj) {
                    float av = arow[jj * NPG + i];
                    acc[jj].x += av * h.x; acc[jj].y += av * h.y;
                    acc[jj].z += av * h.z; acc[jj].w += av * h.w;
                }
            }
        }
        #pragma unroll
        for (int jj = 0; jj < 5; jj++) {
            if (jj < nj) {
                float4 a = acc[jj];
                a.x = elu1(a.x); a.y = elu1(a.y); a.z = elu1(a.z); a.w = elu1(a.w);
                *(float4*)(o1 + (j0 + jj) * ST + 4 * c4) = a;
            }
        }
    }
    __syncthreads();

    // ---- h2 = o1 @ W2 (23 x 48): 4 K-splits x 12 colgroups x 4 rowgroups ----
    // Exactly 192 balanced tasks, 6-row tiles; W2 streamed from L2 (__ldg).
    {
        float* part = h1;                       // [ks][row][col] : 4*23*48 = 4416
        if (tid < 192) {
            int ks = tid / 48;
            int rem = tid - ks * 48;
            int k4 = rem % 12, rg = rem / 12;
            int r0 = rg * 6;
            int nr = (r0 + 6 <= NPG) ? 6 : (NPG - r0);
            int c0 = ks * 48;
            float4 acc[6];
            #pragma unroll
            for (int rr = 0; rr < 6; rr++) acc[rr] = make_float4(0.f, 0.f, 0.f, 0.f);
            #pragma unroll 8
            for (int c = c0; c < c0 + 48; c++) {
                float4 w = __ldg((const float4*)(W2 + c * HID + 4 * k4));
                #pragma unroll
                for (int rr = 0; rr < 6; rr++) {
                    if (rr < nr) {
                        float ov = o1[(r0 + rr) * ST + c];
                        acc[rr].x += ov * w.x; acc[rr].y += ov * w.y;
                        acc[rr].z += ov * w.z; acc[rr].w += ov * w.w;
                    }
                }
            }
            #pragma unroll
            for (int rr = 0; rr < 6; rr++)
                if (rr < nr)
                    *(float4*)(part + ks * 1104 + (r0 + rr) * 48 + 4 * k4) = acc[rr];
        }
        __syncthreads();
        // combine 4 K-partials (deterministic order)
        for (int i4 = tid; i4 < 276; i4 += 256) {
            float4 p0 = ((const float4*)part)[i4];
            float4 p1 = ((const float4*)(part + 1104))[i4];
            float4 p2 = ((const float4*)(part + 2208))[i4];
            float4 p3 = ((const float4*)(part + 3312))[i4];
            float4 s;
            s.x = (p0.x + p1.x) + (p2.x + p3.x);
            s.y = (p0.y + p1.y) + (p2.y + p3.y);
            s.z = (p0.z + p1.z) + (p2.z + p3.z);
            s.w = (p0.w + p1.w) + (p2.w + p3.w);
            ((float4*)h2)[i4] = s;
        }
    }
    __syncthreads();

    // ---- GAT2 logits ----
    if (tid < NPG) {
        const float* hrow = h2 + tid * HID;
        float ss = 0.f, dd = 0.f;
        #pragma unroll
        for (int k4 = 0; k4 < 12; k4++) {
            float4 v = ld4(hrow + 4 * k4);
            float4 s4 = ld4(a2s + 4 * k4);
            float4 d4 = ld4(a2d + 4 * k4);
            ss += v.x * s4.x + v.y * s4.y + v.z * s4.z + v.w * s4.w;
            dd += v.x * d4.x + v.y * d4.y + v.z * d4.z + v.w * d4.w;
        }
        al2s[tid] = ss; al2d[tid] = dd;
    }
    __syncthreads();

    if (tid < NPG) {
        int j = tid;
        float adj = al2d[j];
        float e[NPG];
        float m = -1e30f;
        #pragma unroll
        for (int i = 0; i < NPG; i++) {
            float v = al2s[i] + adj;
            v = (v > 0.f) ? v : 0.2f * v;
            e[i] = v; m = fmaxf(m, v);
        }
        float s = 0.f;
        #pragma unroll
        for (int i = 0; i < NPG; i++) { float w = __expf(e[i] - m); e[i] = w; s += w; }
        float inv = 1.f / (s + 1e-16f);
        #pragma unroll
        for (int i = 0; i < NPG; i++) alpha2[j * 24 + i] = e[i] * inv;
    }
    __syncthreads();

    // ---- aggregate2 + bias + elu -> o2: 12 colgroups x 4-row tiles (72 tasks) ----
    if (tid < 72) {
        int k4 = tid % 12, rg = tid / 12;
        int j0 = rg * 4;
        int nj = (j0 + 4 <= NPG) ? 4 : (NPG - j0);
        float4 bv = ld4(b2s + 4 * k4);
        float4 acc[4];
        #pragma unroll
        for (int jj = 0; jj < 4; jj++) acc[jj] = bv;
        #pragma unroll
        for (int i = 0; i < NPG; i++) {
            float4 h = ld4(h2 + i * HID + 4 * k4);
            #pragma unroll
            for (int jj = 0; jj < 4; jj++) {
                if (jj < nj) {
                    float av = alpha2[(j0 + jj) * 24 + i];
                    acc[jj].x += av * h.x; acc[jj].y += av * h.y;
                    acc[jj].z += av * h.z; acc[jj].w += av * h.w;
                }
            }
        }
        #pragma unroll
        for (int jj = 0; jj < 4; jj++) {
            if (jj < nj) {
                float4 a = acc[jj];
                a.x = elu1(a.x); a.y = elu1(a.y); a.z = elu1(a.z); a.w = elu1(a.w);
                *(float4*)(o2 + (j0 + jj) * HID + 4 * k4) = a;
            }
        }
    }
    __syncthreads();

    // ---- mean/max pooling over nodes -> g_frames ----
    if (tid < HID) {
        float s = 0.f, m = -1e30f;
        #pragma unroll
        for (int j = 0; j < NPG; j++) {
            float v = o2[j * HID + tid];
            s += v; m = fmaxf(m, v);
        }
        g_frames[g * FRAME + tid]       = s * (1.f / (float)NPG);
        g_frames[g * FRAME + HID + tid] = m;
    }
}

// ---------------------------------------------------------------------------
// Kernel 2: gi0 = frames @ Wih0^T + bih0 as a wide GEMM over all 1024 rows.
// ---------------------------------------------------------------------------
#define GI0_GPB 8
__global__ void __launch_bounds__(192) gi0_kernel(const float* __restrict__ Wih0,
                                                  const float* __restrict__ bih0)
{
    extern __shared__ float smem[];
    float* W  = smem;                 // 192 x stride 100 = 19200
    float* xf = smem + G3 * 100;      // 8 x 96 = 768

    const int tid = threadIdx.x;
    const int b0  = blockIdx.x * GI0_GPB;

    for (int i4 = tid; i4 < G3 * 24; i4 += 192) {
        int r = i4 / 24, c4 = i4 - (i4 / 24) * 24;
        *(float4*)(W + r * 100 + 4 * c4) = ld4(Wih0 + r * 96 + 4 * c4);
    }
    for (int i4 = tid; i4 < GI0_GPB * 24; i4 += 192)
        ((float4*)xf)[i4] = ((const float4*)(g_frames + (size_t)b0 * FRAME))[i4];
    __syncthreads();

    const int r = tid;
    float acc[GI0_GPB];
    float bi = bih0[r];
    #pragma unroll
    for (int gg = 0; gg < GI0_GPB; gg++) acc[gg] = bi;
    const float4* wr = (const float4*)(W + r * 100);
    #pragma unroll
    for (int f4 = 0; f4 < 24; f4++) {
        float4 w = wr[f4];
        #pragma unroll
        for (int gg = 0; gg < GI0_GPB; gg++) {
            float4 xv = ld4(xf + gg * 96 + 4 * f4);
            acc[gg] += w.x * xv.x + w.y * xv.y + w.z * xv.z + w.w * xv.w;
        }
    }
    #pragma unroll
    for (int gg = 0; gg < GI0_GPB; gg++)
        g_gi0[(size_t)(b0 + gg) * G3 + r] = acc[gg];
}

// ---------------------------------------------------------------------------
// Kernel 3: 2-layer GRU recurrence + MLP head. One block per batch row.
// ---------------------------------------------------------------------------
__global__ void __launch_bounds__(192) gru_kernel(
    const float* __restrict__ Whh0, const float* __restrict__ bhh0,
    const float* __restrict__ Wih1, const float* __restrict__ bih1,
    const float* __restrict__ Whh1, const float* __restrict__ bhh1,
    const float* __restrict__ Wh1,  const float* __restrict__ bh1,
    const float* __restrict__ Wh2,  const float* __restrict__ bh2,
    float* __restrict__ out)
{
    extern __shared__ float smem[];
    float* Wis  = smem;               // 192 x 68
    float* Whs  = Wis + G3 * 68;      // 192 x 68
    float* gi   = Whs + G3 * 68;      // 16 x 192
    float* seq  = gi  + TT * G3;      // 16 x 64
    float* hbuf = seq + TT * GRUH;    // 64
    float* gh   = hbuf + GRUH;        // 192
    float* q    = gh + G3;            // 32

    const int b = blockIdx.x;
    const int tid = threadIdx.x;

    for (int i4 = tid; i4 < TT * G3 / 4; i4 += 192)
        ((float4*)gi)[i4] = ((const float4*)(g_gi0 + (size_t)b * TT * G3))[i4];
    for (int i4 = tid; i4 < G3 * 16; i4 += 192) {
        int r = i4 >> 4, c4 = i4 & 15;
        *(float4*)(Whs + r * 68 + 4 * c4) = ld4(Whh0 + r * 64 + 4 * c4);
    }
    if (tid < GRUH) hbuf[tid] = 0.f;
    __syncthreads();

    float wr[GRUH];
    #pragma unroll
    for (int c4 = 0; c4 < 16; c4++) {
        float4 v = ld4(Whs + tid * 68 + 4 * c4);
        wr[4 * c4] = v.x; wr[4 * c4 + 1] = v.y; wr[4 * c4 + 2] = v.z; wr[4 * c4 + 3] = v.w;
    }
    float bh = bhh0[tid];
    __syncthreads();

    for (int t = 0; t < TT; t++) {
        float a0 = 0.f, a1 = 0.f, a2 = 0.f, a3 = 0.f;
        #pragma unroll
        for (int u4 = 0; u4 < 16; u4++) {
            float4 hv = ld4(hbuf + 4 * u4);
            a0 += wr[4 * u4]     * hv.x;
            a1 += wr[4 * u4 + 1] * hv.y;
            a2 += wr[4 * u4 + 2] * hv.z;
            a3 += wr[4 * u4 + 3] * hv.w;
        }
        gh[tid] = (a0 + a1) + (a2 + a3) + bh;
        __syncthreads();
        if (tid < GRUH) {
            float gir = gi[t * G3 + tid];
            float giz = gi[t * G3 + GRUH + tid];
            float gin = gi[t * G3 + 2 * GRUH + tid];
            float r = fast_sigmoid(gir + gh[tid]);
            float z = fast_sigmoid(giz + gh[GRUH + tid]);
            float n = fast_tanh(gin + r * gh[2 * GRUH + tid]);
            float hn = (1.f - z) * n + z * hbuf[tid];
            hbuf[tid] = hn;
            seq[t * GRUH + tid] = hn;
        }
        __syncthreads();
    }

    for (int i4 = tid; i4 < G3 * 16; i4 += 192) {
        int r = i4 >> 4, c4 = i4 & 15;
        *(float4*)(Wis + r * 68 + 4 * c4) = ld4(Wih1 + r * 64 + 4 * c4);
        *(float4*)(Whs + r * 68 + 4 * c4) = ld4(Whh1 + r * 64 + 4 * c4);
    }
    __syncthreads();

    {
        float acc[TT];
        float bi = bih1[tid];
        #pragma unroll
        for (int t = 0; t < TT; t++) acc[t] = bi;
        const float4* wrow = (const float4*)(Wis + tid * 68);
        #pragma unroll
        for (int f4 = 0; f4 < 16; f4++) {
            float4 w = wrow[f4];
            #pragma unroll
            for (int t = 0; t < TT; t++) {
                float4 xv = ld4(seq + t * GRUH + 4 * f4);
                acc[t] += w.x * xv.x + w.y * xv.y + w.z * xv.z + w.w * xv.w;
            }
        }
        #pragma unroll
        for (int t = 0; t < TT; t++) gi[t * G3 + tid] = acc[t];
    }

    #pragma unroll
    for (int c4 = 0; c4 < 16; c4++) {
        float4 v = ld4(Whs + tid * 68 + 4 * c4);
        wr[4 * c4] = v.x; wr[4 * c4 + 1] = v.y; wr[4 * c4 + 2] = v.z; wr[4 * c4 + 3] = v.w;
    }
    bh = bhh1[tid];
    if (tid < GRUH) hbuf[tid] = 0.f;
    __syncthreads();

    for (int t = 0; t < TT; t++) {
        float a0 = 0.f, a1 = 0.f, a2 = 0.f, a3 = 0.f;
        #pragma unroll
        for (int u4 = 0; u4 < 16; u4++) {
            float4 hv = ld4(hbuf + 4 * u4);
            a0 += wr[4 * u4]     * hv.x;
            a1 += wr[4 * u4 + 1] * hv.y;
            a2 += wr[4 * u4 + 2] * hv.z;
            a3 += wr[4 * u4 + 3] * hv.w;
        }
        gh[tid] = (a0 + a1) + (a2 + a3) + bh;
        __syncthreads();
        if (tid < GRUH) {
            float gir = gi[t * G3 + tid];
            float giz = gi[t * G3 + GRUH + tid];
            float gin = gi[t * G3 + 2 * GRUH + tid];
            float r = fast_sigmoid(gir + gh[tid]);
            float z = fast_sigmoid(giz + gh[GRUH + tid]);
            float n = fast_tanh(gin + r * gh[2 * GRUH + tid]);
            hbuf[tid] = (1.f - z) * n + z * hbuf[tid];
        }
        __syncthreads();
    }

    if (tid < 32) {
        float acc = bh1[tid];
        #pragma unroll
        for (int u = 0; u < GRUH; u++) acc += hbuf[u] * Wh1[u * 32 + tid];
        q[tid] = fmaxf(acc, 0.f);
    }
    __syncthreads();
    if (tid == 0) {
        float acc = bh2[0];
        #pragma unroll
        for (int m = 0; m < 32; m++) acc += q[m] * Wh2[m];
        out[b] = acc;
    }
}

// ---------------------------------------------------------------------------
extern "C" void kernel_launch(void* const* d_in, const int* in_sizes, int n_in,
                              void* d_out, int out_size)
{
    const float* x    = (const float*)d_in[0];
    const float* W1   = (const float*)d_in[3];
    const float* as1  = (const float*)d_in[4];
    const float* ad1  = (const float*)d_in[5];
    const float* b1   = (const float*)d_in[6];
    const float* W2   = (const float*)d_in[7];
    const float* as2  = (const float*)d_in[8];
    const float* ad2  = (const float*)d_in[9];
    const float* b2   = (const float*)d_in[10];
    const float* Wih0 = (const float*)d_in[11];
    const float* Whh0 = (const float*)d_in[12];
    const float* bih0 = (const float*)d_in[13];
    const float* bhh0 = (const float*)d_in[14];
    const float* Wih1 = (const float*)d_in[15];
    const float* Whh1 = (const float*)d_in[16];
    const float* bih1 = (const float*)d_in[17];
    const float* bhh1 = (const float*)d_in[18];
    const float* Wh1  = (const float*)d_in[19];
    const float* bh1  = (const float*)d_in[20];
    const float* Wh2  = (const float*)d_in[21];
    const float* bh2  = (const float*)d_in[22];

    const int GAT_SMEM = 17240 * 4;                          // 68960
    const int GI0_SMEM = (G3 * 100 + GI0_GPB * FRAME) * 4;
    const int GRU_SMEM = (2 * G3 * 68 + TT * G3 + TT * GRUH + GRUH + G3 + 32) * 4;

    static bool attrs_set = false;
    if (!attrs_set) {
        cudaFuncSetAttribute(gat_kernel, cudaFuncAttributeMaxDynamicSharedMemorySize, GAT_SMEM);
        cudaFuncSetAttribute(gi0_kernel, cudaFuncAttributeMaxDynamicSharedMemorySize, GI0_SMEM);
        cudaFuncSetAttribute(gru_kernel, cudaFuncAttributeMaxDynamicSharedMemorySize, GRU_SMEM);
        attrs_set = true;
    }

    gat_kernel<<<NGRAPH, 256, GAT_SMEM>>>(x, W1, as1, ad1, b1, W2, as2, ad2, b2);
    gi0_kernel<<<NGRAPH / GI0_GPB, 192, GI0_SMEM>>>(Wih0, bih0);
    gru_kernel<<<BB, 192, GRU_SMEM>>>(Whh0, bhh0, Wih1, bih1, Whh1, bhh1,
                                      Wh1, bh1, Wh2, bh2, (float*)d_out);
}

// round 5
// speedup vs baseline: 2.1116x; 1.0778x over previous
#include <cuda_runtime.h>

#define NPG 23
#define NF 11
#define HID 48
#define C1 192
#define NGRAPH 1024
#define GRUH 64
#define G3 192
#define TT 16
#define BB 64
#define FRAME 96
#define ST 196           // padded float4-aligned stride for 192-wide rows

__device__ float g_frames[NGRAPH * FRAME];

__device__ __forceinline__ float4 ld4(const float* p) { return *(const float4*)p; }
__device__ __forceinline__ float4 ld4g(const float* p) { return __ldg((const float4*)p); }

__device__ __forceinline__ float fast_sigmoid(float x) {
    return 1.f / (1.f + __expf(-x));
}
__device__ __forceinline__ float fast_tanh(float x) {
    float e = __expf(-2.f * x);
    return (1.f - e) / (1.f + e);
}
__device__ __forceinline__ float elu1(float v) {
    return v > 0.f ? v : (__expf(v) - 1.f);
}
// a += v (row of 4 c-values) * W2 rows w0..w3 (each 4 k-values)
__device__ __forceinline__ void fma_row(float4& a, float4 v,
                                        float4 w0, float4 w1, float4 w2, float4 w3) {
    a.x += v.x * w0.x + v.y * w1.x + v.z * w2.x + v.w * w3.x;
    a.y += v.x * w0.y + v.y * w1.y + v.z * w2.y + v.w * w3.y;
    a.z += v.x * w0.z + v.y * w1.z + v.z * w2.z + v.w * w3.z;
    a.w += v.x * w0.w + v.y * w1.w + v.z * w2.w + v.w * w3.w;
}

// ---------------------------------------------------------------------------
// Kernel 1: fused GAT1 + GAT2 + pooling. One block per 23-node group.
// All weights/biases streamed from L2 (__ldg, uniform across blocks).
// Smem = 46.4KB -> 4 blocks/SM. GAT2 scratch aliases the dead o1 region.
// ---------------------------------------------------------------------------
__global__ void __launch_bounds__(256, 4) gat_kernel(
    const float* __restrict__ x,
    const float* __restrict__ W1,  const float* __restrict__ as1,
    const float* __restrict__ ad1, const float* __restrict__ b1,
    const float* __restrict__ W2,  const float* __restrict__ as2,
    const float* __restrict__ ad2, const float* __restrict__ b2)
{
    extern __shared__ float sm[];
    float* xs    = sm;              // 276 (23 x stride 12)
    float* h1    = xs + 276;        // 23*196 = 4508 ; later: h2 partials (2*1104)
    float* o1    = h1 + 4508;       // 4508 ; later: h2 | al2 | alpha2 | o2
    float* als   = o1 + 4508;       // 96
    float* ald   = als + 96;        // 96
    float* alpha = ald + 96;        // 4*23*23 = 2116
    // total 11600 floats = 46400 B
    // aliases into the o1 region (o1 dead after the h2-partial phase):
    float* h2     = o1;             // 1104
    float* al2s   = o1 + 1104;      // 24
    float* al2d   = o1 + 1128;      // 24
    float* alpha2 = o1 + 1152;      // 23*24 = 552
    float* o2     = o1 + 1704;      // 1104

    const int tid = threadIdx.x;
    const int g   = blockIdx.x;

    // ---- load this group's features (only block-specific data in smem) ----
    const float* xg = x + (size_t)g * (NPG * NF);
    for (int i = tid; i < NPG * NF; i += 256) {
        int r = i / NF, c = i - r * NF;
        xs[r * 12 + c] = xg[i];
    }
    __syncthreads();

    // ---- h1 = x @ W1 (23 x 192): 48 colgroups x 5-row tiles, W1 from L2 ----
    if (tid < 240) {
        int c4 = tid % 48, rg = tid / 48;
        int r0 = rg * 5;
        int nr = (r0 + 5 <= NPG) ? 5 : (NPG - r0);
        float4 acc[5];
        #pragma unroll
        for (int rr = 0; rr < 5; rr++) acc[rr] = make_float4(0.f, 0.f, 0.f, 0.f);
        #pragma unroll
        for (int f = 0; f < NF; f++) {
            float4 w = ld4g(W1 + f * C1 + 4 * c4);
            #pragma unroll
            for (int rr = 0; rr < 5; rr++) {
                if (rr < nr) {
                    float xv = xs[(r0 + rr) * 12 + f];
                    acc[rr].x += xv * w.x; acc[rr].y += xv * w.y;
                    acc[rr].z += xv * w.z; acc[rr].w += xv * w.w;
                }
            }
        }
        #pragma unroll
        for (int rr = 0; rr < 5; rr++)
            if (rr < nr) *(float4*)(h1 + (r0 + rr) * ST + 4 * c4) = acc[rr];
    }
    __syncthreads();

    // ---- attention logits per (node, head); as1/ad1 from L2 ----
    if (tid < NPG * 4) {
        int i = tid >> 2, hd = tid & 3;
        const float* hrow = h1 + i * ST + hd * HID;
        float ss = 0.f, dd = 0.f;
        #pragma unroll
        for (int k4 = 0; k4 < 12; k4++) {
            float4 v  = ld4(hrow + 4 * k4);
            float4 s4 = ld4g(as1 + hd * HID + 4 * k4);
            float4 d4 = ld4g(ad1 + hd * HID + 4 * k4);
            ss += v.x * s4.x + v.y * s4.y + v.z * s4.z + v.w * s4.w;
            dd += v.x * d4.x + v.y * d4.y + v.z * d4.z + v.w * d4.w;
        }
        als[tid] = ss; ald[tid] = dd;
    }
    __syncthreads();

    // ---- softmax over sources for each (dst j, head) ----
    if (tid < NPG * 4) {
        int j = tid >> 2, hd = tid & 3;
        float adj = ald[j * 4 + hd];
        float e[NPG];
        float m = -1e30f;
        #pragma unroll
        for (int i = 0; i < NPG; i++) {
            float v = als[i * 4 + hd] + adj;
            v = (v > 0.f) ? v : 0.2f * v;
            e[i] = v; m = fmaxf(m, v);
        }
        float s = 0.f;
        #pragma unroll
        for (int i = 0; i < NPG; i++) { float w = __expf(e[i] - m); e[i] = w; s += w; }
        float inv = 1.f / (s + 1e-16f);
        #pragma unroll
        for (int i = 0; i < NPG; i++) alpha[(hd * NPG + j) * NPG + i] = e[i] * inv;
    }
    __syncthreads();

    // ---- aggregate1 + bias + elu -> o1: 48 colgroups x 5-dst-row tiles ----
    if (tid < 240) {
        int c4 = tid % 48, rg = tid / 48;
        int j0 = rg * 5;
        int nj = (j0 + 5 <= NPG) ? 5 : (NPG - j0);
        int hd = c4 / 12;
        float4 bv = ld4g(b1 + 4 * c4);
        float4 acc[5];
        #pragma unroll
        for (int jj = 0; jj < 5; jj++) acc[jj] = bv;
        const float* arow = alpha + (hd * NPG + j0) * NPG;
        #pragma unroll
        for (int i = 0; i < NPG; i++) {
            float4 h = ld4(h1 + i * ST + 4 * c4);
            #pragma unroll
            for (int jj = 0; jj < 5; jj++) {
                if (jj < nj) {
                    float av = arow[jj * NPG + i];
                    acc[jj].x += av * h.x; acc[jj].y += av * h.y;
                    acc[jj].z += av * h.z; acc[jj].w += av * h.w;
                }
            }
        }
        #pragma unroll
        for (int jj = 0; jj < 5; jj++) {
            if (jj < nj) {
                float4 a = acc[jj];
                a.x = elu1(a.x); a.y = elu1(a.y); a.z = elu1(a.z); a.w = elu1(a.w);
                *(float4*)(o1 + (j0 + jj) * ST + 4 * c4) = a;
            }
        }
    }
    __syncthreads();

    // ---- h2 = o1 @ W2 (23x48): 2 K-splits x 12 k4 x 8 rowgroups(3) = 192 tasks
    // o1 read as float4; W2 lane-contiguous LDG.128 from L2.
    {
        float* part = h1;                     // [ks][row][col] : 2*23*48 = 2208
        if (tid < 192) {
            int k4 = tid % 12;
            int rg = (tid / 12) % 8;
            int ks = tid / 96;
            int r0 = rg * 3;
            int nr = (r0 + 3 <= NPG) ? 3 : (NPG - r0);
            int r1 = (r0 + 1 < NPG) ? r0 + 1 : NPG - 1;   // clamped (result masked)
            int r2 = (r0 + 2 < NPG) ? r0 + 2 : NPG - 1;
            int c0 = ks * 96;
            float4 a0 = make_float4(0.f,0.f,0.f,0.f);
            float4 a1 = a0, a2 = a0;
            const float* p0 = o1 + r0 * ST;
            const float* p1 = o1 + r1 * ST;
            const float* p2 = o1 + r2 * ST;
            #pragma unroll 6
            for (int c4i = 0; c4i < 24; c4i++) {
                int c = c0 + 4 * c4i;
                float4 v0 = ld4(p0 + c);
                float4 v1 = ld4(p1 + c);
                float4 v2 = ld4(p2 + c);
                const float* wp = W2 + c * HID + 4 * k4;
                float4 w0 = ld4g(wp);
                float4 w1 = ld4g(wp + HID);
                float4 w2 = ld4g(wp + 2 * HID);
                float4 w3 = ld4g(wp + 3 * HID);
                fma_row(a0, v0, w0, w1, w2, w3);
                fma_row(a1, v1, w0, w1, w2, w3);
                fma_row(a2, v2, w0, w1, w2, w3);
            }
            float* dst = part + ks * 1104 + r0 * 48 + 4 * k4;
            *(float4*)(dst) = a0;
            if (nr > 1) *(float4*)(dst + 48) = a1;
            if (nr > 2) *(float4*)(dst + 96) = a2;
        }
        __syncthreads();
        // combine the 2 K-partials (deterministic) -> h2 (aliases o1 base)
        for (int i4 = tid; i4 < 276; i4 += 256) {
            float4 q0 = ((const float4*)part)[i4];
            float4 q1 = ((const float4*)(part + 1104))[i4];
            float4 s;
            s.x = q0.x + q1.x; s.y = q0.y + q1.y;
            s.z = q0.z + q1.z; s.w = q0.w + q1.w;
            ((float4*)h2)[i4] = s;
        }
    }
    __syncthreads();

    // ---- GAT2 logits (as2/ad2 from L2) ----
    if (tid < NPG) {
        const float* hrow = h2 + tid * HID;
        float ss = 0.f, dd = 0.f;
        #pragma unroll
        for (int k4 = 0; k4 < 12; k4++) {
            float4 v  = ld4(hrow + 4 * k4);
            float4 s4 = ld4g(as2 + 4 * k4);
            float4 d4 = ld4g(ad2 + 4 * k4);
            ss += v.x * s4.x + v.y * s4.y + v.z * s4.z + v.w * s4.w;
            dd += v.x * d4.x + v.y * d4.y + v.z * d4.z + v.w * d4.w;
        }
        al2s[tid] = ss; al2d[tid] = dd;
    }
    __syncthreads();

    if (tid < NPG) {
        int j = tid;
        float adj = al2d[j];
        float e[NPG];
        float m = -1e30f;
        #pragma unroll
        for (int i = 0; i < NPG; i++) {
            float v = al2s[i] + adj;
            v = (v > 0.f) ? v : 0.2f * v;
            e[i] = v; m = fmaxf(m, v);
        }
        float s = 0.f;
        #pragma unroll
        for (int i = 0; i < NPG; i++) { float w = __expf(e[i] - m); e[i] = w; s += w; }
        float inv = 1.f / (s + 1e-16f);
        #pragma unroll
        for (int i = 0; i < NPG; i++) alpha2[j * 24 + i] = e[i] * inv;
    }
    __syncthreads();

    // ---- aggregate2 + bias + elu -> o2: 12 colgroups x 4-row tiles ----
    if (tid < 72) {
        int k4 = tid % 12, rg = tid / 12;
        int j0 = rg * 4;
        int nj = (j0 + 4 <= NPG) ? 4 : (NPG - j0);
        float4 bv = ld4g(b2 + 4 * k4);
        float4 acc[4];
        #pragma unroll
        for (int jj = 0; jj < 4; jj++) acc[jj] = bv;
        #pragma unroll
        for (int i = 0; i < NPG; i++) {
            float4 h = ld4(h2 + i * HID + 4 * k4);
            #pragma unroll
            for (int jj = 0; jj < 4; jj++) {
                if (jj < nj) {
                    float av = alpha2[(j0 + jj) * 24 + i];
                    acc[jj].x += av * h.x; acc[jj].y += av * h.y;
                    acc[jj].z += av * h.z; acc[jj].w += av * h.w;
                }
            }
        }
        #pragma unroll
        for (int jj = 0; jj < 4; jj++) {
            if (jj < nj) {
                float4 a = acc[jj];
                a.x = elu1(a.x); a.y = elu1(a.y); a.z = elu1(a.z); a.w = elu1(a.w);
                *(float4*)(o2 + (j0 + jj) * HID + 4 * k4) = a;
            }
        }
    }
    __syncthreads();

    // ---- mean/max pooling over nodes -> g_frames ----
    if (tid < HID) {
        float s = 0.f, m = -1e30f;
        #pragma unroll
        for (int j = 0; j < NPG; j++) {
            float v = o2[j * HID + tid];
            s += v; m = fmaxf(m, v);
        }
        g_frames[g * FRAME + tid]       = s * (1.f / (float)NPG);
        g_frames[g * FRAME + HID + tid] = m;
    }
}

// ---------------------------------------------------------------------------
// Kernel 2: gi0 (in-block) + 2-layer GRU recurrence + MLP head.
// One block per batch row, 192 threads.
// ---------------------------------------------------------------------------
__global__ void __launch_bounds__(192) gru_kernel(
    const float* __restrict__ Wih0, const float* __restrict__ bih0,
    const float* __restrict__ Whh0, const float* __restrict__ bhh0,
    const float* __restrict__ Wih1, const float* __restrict__ bih1,
    const float* __restrict__ Whh1, const float* __restrict__ bhh1,
    const float* __restrict__ Wh1,  const float* __restrict__ bh1,
    const float* __restrict__ Wh2,  const float* __restrict__ bh2,
    float* __restrict__ out)
{
    extern __shared__ float smem[];
    float* Wis  = smem;               // 192 x 68 (layer-1 Wih staging)
    float* Whs  = Wis + G3 * 68;      // 192 x 68 (Whh staging)
    float* gi   = Whs + G3 * 68;      // 16 x 192
    float* xb   = gi  + TT * G3;      // 16 x 96 (frames; broadcast-read)
    float* seq  = xb  + TT * FRAME;   // 16 x 64
    float* hbuf = seq + TT * GRUH;    // 64
    float* gh   = hbuf + GRUH;        // 192
    float* q    = gh + G3;            // 32

    const int b = blockIdx.x;
    const int tid = threadIdx.x;

    // ---- prologue loads ----
    for (int i4 = tid; i4 < TT * FRAME / 4; i4 += 192)
        ((float4*)xb)[i4] = ((const float4*)(g_frames + (size_t)b * TT * FRAME))[i4];
    for (int i4 = tid; i4 < G3 * 16; i4 += 192) {
        int r = i4 >> 4, c4 = i4 & 15;
        *(float4*)(Whs + r * 68 + 4 * c4) = ld4(Whh0 + r * 64 + 4 * c4);
    }
    if (tid < GRUH) hbuf[tid] = 0.f;
    __syncthreads();

    // ---- gi0 in-block: row tid of Wih0 against all 16 frames ----
    {
        float acc[TT];
        float bi = bih0[tid];
        #pragma unroll
        for (int t = 0; t < TT; t++) acc[t] = bi;
        const float* wrow = Wih0 + tid * FRAME;
        #pragma unroll
        for (int f4 = 0; f4 < 24; f4++) {
            float4 w = ld4g(wrow + 4 * f4);
            #pragma unroll
            for (int t = 0; t < TT; t++) {
                float4 xv = ld4(xb + t * FRAME + 4 * f4);
                acc[t] += w.x * xv.x + w.y * xv.y + w.z * xv.z + w.w * xv.w;
            }
        }
        #pragma unroll
        for (int t = 0; t < TT; t++) gi[t * G3 + tid] = acc[t];
    }

    float wr[GRUH];
    #pragma unroll
    for (int c4 = 0; c4 < 16; c4++) {
        float4 v = ld4(Whs + tid * 68 + 4 * c4);
        wr[4 * c4] = v.x; wr[4 * c4 + 1] = v.y; wr[4 * c4 + 2] = v.z; wr[4 * c4 + 3] = v.w;
    }
    float bh = bhh0[tid];
    __syncthreads();

    // ---- layer 0 recurrence (writes seq) ----
    for (int t = 0; t < TT; t++) {
        float a0 = 0.f, a1 = 0.f, a2 = 0.f, a3 = 0.f;
        #pragma unroll
        for (int u4 = 0; u4 < 16; u4++) {
            float4 hv = ld4(hbuf + 4 * u4);
            a0 += wr[4 * u4]     * hv.x;
            a1 += wr[4 * u4 + 1] * hv.y;
            a2 += wr[4 * u4 + 2] * hv.z;
            a3 += wr[4 * u4 + 3] * hv.w;
        }
        gh[tid] = (a0 + a1) + (a2 + a3) + bh;
        __syncthreads();
        if (tid < GRUH) {
            float gir = gi[t * G3 + tid];
            float giz = gi[t * G3 + GRUH + tid];
            float gin = gi[t * G3 + 2 * GRUH + tid];
            float r = fast_sigmoid(gir + gh[tid]);
            float z = fast_sigmoid(giz + gh[GRUH + tid]);
            float n = fast_tanh(gin + r * gh[2 * GRUH + tid]);
            float hn = (1.f - z) * n + z * hbuf[tid];
            hbuf[tid] = hn;
            seq[t * GRUH + tid] = hn;
        }
        __syncthreads();
    }

    // ---- load layer-1 weights ----
    for (int i4 = tid; i4 < G3 * 16; i4 += 192) {
        int r = i4 >> 4, c4 = i4 & 15;
        *(float4*)(Wis + r * 68 + 4 * c4) = ld4(Wih1 + r * 64 + 4 * c4);
        *(float4*)(Whs + r * 68 + 4 * c4) = ld4(Whh1 + r * 64 + 4 * c4);
    }
    __syncthreads();

    // ---- gi1 for all 16 steps ----
    {
        float acc[TT];
        float bi = bih1[tid];
        #pragma unroll
        for (int t = 0; t < TT; t++) acc[t] = bi;
        const float4* wrow = (const float4*)(Wis + tid * 68);
        #pragma unroll
        for (int f4 = 0; f4 < 16; f4++) {
            float4 w = wrow[f4];
            #pragma unroll
            for (int t = 0; t < TT; t++) {
                float4 xv = ld4(seq + t * GRUH + 4 * f4);
                acc[t] += w.x * xv.x + w.y * xv.y + w.z * xv.z + w.w * xv.w;
            }
        }
        #pragma unroll
        for (int t = 0; t < TT; t++) gi[t * G3 + tid] = acc[t];
    }

    #pragma unroll
    for (int c4 = 0; c4 < 16; c4++) {
        float4 v = ld4(Whs + tid * 68 + 4 * c4);
        wr[4 * c4] = v.x; wr[4 * c4 + 1] = v.y; wr[4 * c4 + 2] = v.z; wr[4 * c4 + 3] = v.w;
    }
    bh = bhh1[tid];
    if (tid < GRUH) hbuf[tid] = 0.f;
    __syncthreads();

    // ---- layer 1 recurrence (only final h needed) ----
    for (int t = 0; t < TT; t++) {
        float a0 = 0.f, a1 = 0.f, a2 = 0.f, a3 = 0.f;
        #pragma unroll
        for (int u4 = 0; u4 < 16; u4++) {
            float4 hv = ld4(hbuf + 4 * u4);
            a0 += wr[4 * u4]     * hv.x;
            a1 += wr[4 * u4 + 1] * hv.y;
            a2 += wr[4 * u4 + 2] * hv.z;
            a3 += wr[4 * u4 + 3] * hv.w;
        }
        gh[tid] = (a0 + a1) + (a2 + a3) + bh;
        __syncthreads();
        if (tid < GRUH) {
            float gir = gi[t * G3 + tid];
            float giz = gi[t * G3 + GRUH + tid];
            float gin = gi[t * G3 + 2 * GRUH + tid];
            float r = fast_sigmoid(gir + gh[tid]);
            float z = fast_sigmoid(giz + gh[GRUH + tid]);
            float n = fast_tanh(gin + r * gh[2 * GRUH + tid]);
            hbuf[tid] = (1.f - z) * n + z * hbuf[tid];
        }
        __syncthreads();
    }

    // ---- MLP head ----
    if (tid < 32) {
        float acc = bh1[tid];
        #pragma unroll
        for (int u = 0; u < GRUH; u++) acc += hbuf[u] * Wh1[u * 32 + tid];
        q[tid] = fmaxf(acc, 0.f);
    }
    __syncthreads();
    if (tid == 0) {
        float acc = bh2[0];
        #pragma unroll
        for (int m = 0; m < 32; m++) acc += q[m] * Wh2[m];
        out[b] = acc;
    }
}

// ---------------------------------------------------------------------------
extern "C" void kernel_launch(void* const* d_in, const int* in_sizes, int n_in,
                              void* d_out, int out_size)
{
    const float* x    = (const float*)d_in[0];
    const float* W1   = (const float*)d_in[3];
    const float* as1  = (const float*)d_in[4];
    const float* ad1  = (const float*)d_in[5];
    const float* b1   = (const float*)d_in[6];
    const float* W2   = (const float*)d_in[7];
    const float* as2  = (const float*)d_in[8];
    const float* ad2  = (const float*)d_in[9];
    const float* b2   = (const float*)d_in[10];
    const float* Wih0 = (const float*)d_in[11];
    const float* Whh0 = (const float*)d_in[12];
    const float* bih0 = (const float*)d_in[13];
    const float* bhh0 = (const float*)d_in[14];
    const float* Wih1 = (const float*)d_in[15];
    const float* Whh1 = (const float*)d_in[16];
    const float* bih1 = (const float*)d_in[17];
    const float* bhh1 = (const float*)d_in[18];
    const float* Wh1  = (const float*)d_in[19];
    const float* bh1  = (const float*)d_in[20];
    const float* Wh2  = (const float*)d_in[21];
    const float* bh2  = (const float*)d_in[22];

    const int GAT_SMEM = 11600 * 4;   // 46400 B -> 4 blocks/SM
    const int GRU_SMEM = (2 * G3 * 68 + TT * G3 + TT * FRAME + TT * GRUH
                          + GRUH + G3 + 32) * 4;

    static bool attrs_set = false;
    if (!attrs_set) {
        cudaFuncSetAttribute(gat_kernel, cudaFuncAttributeMaxDynamicSharedMemorySize, GAT_SMEM);
        cudaFuncSetAttribute(gru_kernel, cudaFuncAttributeMaxDynamicSharedMemorySize, GRU_SMEM);
        attrs_set = true;
    }

    gat_kernel<<<NGRAPH, 256, GAT_SMEM>>>(x, W1, as1, ad1, b1, W2, as2, ad2, b2);
    gru_kernel<<<BB, 192, GRU_SMEM>>>(Wih0, bih0, Whh0, bhh0,
                                      Wih1, bih1, Whh1, bhh1,
                                      Wh1, bh1, Wh2, bh2, (float*)d_out);
}

// round 6
// speedup vs baseline: 2.1151x; 1.0016x over previous
#include <cuda_runtime.h>

#define NPG 23
#define NF 11
#define HID 48
#define C1 192
#define NGRAPH 1024
#define GRUH 64
#define G3 192
#define TT 16
#define BB 64
#define FRAME 96
#define ST 196           // padded float4-aligned stride for 192-wide rows

__device__ float g_frames[NGRAPH * FRAME];
__device__ float g_gi0[NGRAPH * G3];

__device__ __forceinline__ float4 ld4(const float* p) { return *(const float4*)p; }
__device__ __forceinline__ float4 ld4g(const float* p) { return __ldg((const float4*)p); }

__device__ __forceinline__ float fast_sigmoid(float x) {
    return 1.f / (1.f + __expf(-x));
}
__device__ __forceinline__ float fast_tanh(float x) {
    float e = __expf(-2.f * x);
    return (1.f - e) / (1.f + e);
}
__device__ __forceinline__ float elu1(float v) {
    return v > 0.f ? v : (__expf(v) - 1.f);
}
__device__ __forceinline__ void fma_row(float4& a, float4 v,
                                        float4 w0, float4 w1, float4 w2, float4 w3) {
    a.x += v.x * w0.x + v.y * w1.x + v.z * w2.x + v.w * w3.x;
    a.y += v.x * w0.y + v.y * w1.y + v.z * w2.y + v.w * w3.y;
    a.z += v.x * w0.z + v.y * w1.z + v.z * w2.z + v.w * w3.z;
    a.w += v.x * w0.w + v.y * w1.w + v.z * w2.w + v.w * w3.w;
}

// ---------------------------------------------------------------------------
// Kernel 1: fused GAT1 + GAT2 + pooling (unchanged from round 5).
// ---------------------------------------------------------------------------
__global__ void __launch_bounds__(256, 4) gat_kernel(
    const float* __restrict__ x,
    const float* __restrict__ W1,  const float* __restrict__ as1,
    const float* __restrict__ ad1, const float* __restrict__ b1,
    const float* __restrict__ W2,  const float* __restrict__ as2,
    const float* __restrict__ ad2, const float* __restrict__ b2)
{
    extern __shared__ float sm[];
    float* xs    = sm;              // 276
    float* h1    = xs + 276;        // 4508 ; later h2 partials
    float* o1    = h1 + 4508;       // 4508 ; later h2|al2|alpha2|o2
    float* als   = o1 + 4508;       // 96
    float* ald   = als + 96;        // 96
    float* alpha = ald + 96;        // 2116
    float* h2     = o1;
    float* al2s   = o1 + 1104;
    float* al2d   = o1 + 1128;
    float* alpha2 = o1 + 1152;
    float* o2     = o1 + 1704;

    const int tid = threadIdx.x;
    const int g   = blockIdx.x;

    const float* xg = x + (size_t)g * (NPG * NF);
    for (int i = tid; i < NPG * NF; i += 256) {
        int r = i / NF, c = i - r * NF;
        xs[r * 12 + c] = xg[i];
    }
    __syncthreads();

    if (tid < 240) {
        int c4 = tid % 48, rg = tid / 48;
        int r0 = rg * 5;
        int nr = (r0 + 5 <= NPG) ? 5 : (NPG - r0);
        float4 acc[5];
        #pragma unroll
        for (int rr = 0; rr < 5; rr++) acc[rr] = make_float4(0.f, 0.f, 0.f, 0.f);
        #pragma unroll
        for (int f = 0; f < NF; f++) {
            float4 w = ld4g(W1 + f * C1 + 4 * c4);
            #pragma unroll
            for (int rr = 0; rr < 5; rr++) {
                if (rr < nr) {
                    float xv = xs[(r0 + rr) * 12 + f];
                    acc[rr].x += xv * w.x; acc[rr].y += xv * w.y;
                    acc[rr].z += xv * w.z; acc[rr].w += xv * w.w;
                }
            }
        }
        #pragma unroll
        for (int rr = 0; rr < 5; rr++)
            if (rr < nr) *(float4*)(h1 + (r0 + rr) * ST + 4 * c4) = acc[rr];
    }
    __syncthreads();

    if (tid < NPG * 4) {
        int i = tid >> 2, hd = tid & 3;
        const float* hrow = h1 + i * ST + hd * HID;
        float ss = 0.f, dd = 0.f;
        #pragma unroll
        for (int k4 = 0; k4 < 12; k4++) {
            float4 v  = ld4(hrow + 4 * k4);
            float4 s4 = ld4g(as1 + hd * HID + 4 * k4);
            float4 d4 = ld4g(ad1 + hd * HID + 4 * k4);
            ss += v.x * s4.x + v.y * s4.y + v.z * s4.z + v.w * s4.w;
            dd += v.x * d4.x + v.y * d4.y + v.z * d4.z + v.w * d4.w;
        }
        als[tid] = ss; ald[tid] = dd;
    }
    __syncthreads();

    if (tid < NPG * 4) {
        int j = tid >> 2, hd = tid & 3;
        float adj = ald[j * 4 + hd];
        float e[NPG];
        float m = -1e30f;
        #pragma unroll
        for (int i = 0; i < NPG; i++) {
            float v = als[i * 4 + hd] + adj;
            v = (v > 0.f) ? v : 0.2f * v;
            e[i] = v; m = fmaxf(m, v);
        }
        float s = 0.f;
        #pragma unroll
        for (int i = 0; i < NPG; i++) { float w = __expf(e[i] - m); e[i] = w; s += w; }
        float inv = 1.f / (s + 1e-16f);
        #pragma unroll
        for (int i = 0; i < NPG; i++) alpha[(hd * NPG + j) * NPG + i] = e[i] * inv;
    }
    __syncthreads();

    if (tid < 240) {
        int c4 = tid % 48, rg = tid / 48;
        int j0 = rg * 5;
        int nj = (j0 + 5 <= NPG) ? 5 : (NPG - j0);
        int hd = c4 / 12;
        float4 bv = ld4g(b1 + 4 * c4);
        float4 acc[5];
        #pragma unroll
        for (int jj = 0; jj < 5; jj++) acc[jj] = bv;
        const float* arow = alpha + (hd * NPG + j0) * NPG;
        #pragma unroll
        for (int i = 0; i < NPG; i++) {
            float4 h = ld4(h1 + i * ST + 4 * c4);
            #pragma unroll
            for (int jj = 0; jj < 5; jj++) {
                if (jj < nj) {
                    float av = arow[jj * NPG + i];
                    acc[jj].x += av * h.x; acc[jj].y += av * h.y;
                    acc[jj].z += av * h.z; acc[jj].w += av * h.w;
                }
            }
        }
        #pragma unroll
        for (int jj = 0; jj < 5; jj++) {
            if (jj < nj) {
                float4 a = acc[jj];
                a.x = elu1(a.x); a.y = elu1(a.y); a.z = elu1(a.z); a.w = elu1(a.w);
                *(float4*)(o1 + (j0 + jj) * ST + 4 * c4) = a;
            }
        }
    }
    __syncthreads();

    {
        float* part = h1;
        if (tid < 192) {
            int k4 = tid % 12;
            int rg = (tid / 12) % 8;
            int ks = tid / 96;
            int r0 = rg * 3;
            int nr = (r0 + 3 <= NPG) ? 3 : (NPG - r0);
            int r1 = (r0 + 1 < NPG) ? r0 + 1 : NPG - 1;
            int r2 = (r0 + 2 < NPG) ? r0 + 2 : NPG - 1;
            int c0 = ks * 96;
            float4 a0 = make_float4(0.f,0.f,0.f,0.f);
            float4 a1 = a0, a2 = a0;
            const float* p0 = o1 + r0 * ST;
            const float* p1 = o1 + r1 * ST;
            const float* p2 = o1 + r2 * ST;
            #pragma unroll 6
            for (int c4i = 0; c4i < 24; c4i++) {
                int c = c0 + 4 * c4i;
                float4 v0 = ld4(p0 + c);
                float4 v1 = ld4(p1 + c);
                float4 v2 = ld4(p2 + c);
                const float* wp = W2 + c * HID + 4 * k4;
                float4 w0 = ld4g(wp);
                float4 w1 = ld4g(wp + HID);
                float4 w2 = ld4g(wp + 2 * HID);
                float4 w3 = ld4g(wp + 3 * HID);
                fma_row(a0, v0, w0, w1, w2, w3);
                fma_row(a1, v1, w0, w1, w2, w3);
                fma_row(a2, v2, w0, w1, w2, w3);
            }
            float* dst = part + ks * 1104 + r0 * 48 + 4 * k4;
            *(float4*)(dst) = a0;
            if (nr > 1) *(float4*)(dst + 48) = a1;
            if (nr > 2) *(float4*)(dst + 96) = a2;
        }
        __syncthreads();
        for (int i4 = tid; i4 < 276; i4 += 256) {
            float4 q0 = ((const float4*)part)[i4];
            float4 q1 = ((const float4*)(part + 1104))[i4];
            float4 s;
            s.x = q0.x + q1.x; s.y = q0.y + q1.y;
            s.z = q0.z + q1.z; s.w = q0.w + q1.w;
            ((float4*)h2)[i4] = s;
        }
    }
    __syncthreads();

    if (tid < NPG) {
        const float* hrow = h2 + tid * HID;
        float ss = 0.f, dd = 0.f;
        #pragma unroll
        for (int k4 = 0; k4 < 12; k4++) {
            float4 v  = ld4(hrow + 4 * k4);
            float4 s4 = ld4g(as2 + 4 * k4);
            float4 d4 = ld4g(ad2 + 4 * k4);
            ss += v.x * s4.x + v.y * s4.y + v.z * s4.z + v.w * s4.w;
            dd += v.x * d4.x + v.y * d4.y + v.z * d4.z + v.w * d4.w;
        }
        al2s[tid] = ss; al2d[tid] = dd;
    }
    __syncthreads();

    if (tid < NPG) {
        int j = tid;
        float adj = al2d[j];
        float e[NPG];
        float m = -1e30f;
        #pragma unroll
        for (int i = 0; i < NPG; i++) {
            float v = al2s[i] + adj;
            v = (v > 0.f) ? v : 0.2f * v;
            e[i] = v; m = fmaxf(m, v);
        }
        float s = 0.f;
        #pragma unroll
        for (int i = 0; i < NPG; i++) { float w = __expf(e[i] - m); e[i] = w; s += w; }
        float inv = 1.f / (s + 1e-16f);
        #pragma unroll
        for (int i = 0; i < NPG; i++) alpha2[j * 24 + i] = e[i] * inv;
    }
    __syncthreads();

    if (tid < 72) {
        int k4 = tid % 12, rg = tid / 12;
        int j0 = rg * 4;
        int nj = (j0 + 4 <= NPG) ? 4 : (NPG - j0);
        float4 bv = ld4g(b2 + 4 * k4);
        float4 acc[4];
        #pragma unroll
        for (int jj = 0; jj < 4; jj++) acc[jj] = bv;
        #pragma unroll
        for (int i = 0; i < NPG; i++) {
            float4 h = ld4(h2 + i * HID + 4 * k4);
            #pragma unroll
            for (int jj = 0; jj < 4; jj++) {
                if (jj < nj) {
                    float av = alpha2[(j0 + jj) * 24 + i];
                    acc[jj].x += av * h.x; acc[jj].y += av * h.y;
                    acc[jj].z += av * h.z; acc[jj].w += av * h.w;
                }
            }
        }
        #pragma unroll
        for (int jj = 0; jj < 4; jj++) {
            if (jj < nj) {
                float4 a = acc[jj];
                a.x = elu1(a.x); a.y = elu1(a.y); a.z = elu1(a.z); a.w = elu1(a.w);
                *(float4*)(o2 + (j0 + jj) * HID + 4 * k4) = a;
            }
        }
    }
    __syncthreads();

    if (tid < HID) {
        float s = 0.f, m = -1e30f;
        #pragma unroll
        for (int j = 0; j < NPG; j++) {
            float v = o2[j * HID + tid];
            s += v; m = fmaxf(m, v);
        }
        g_frames[g * FRAME + tid]       = s * (1.f / (float)NPG);
        g_frames[g * FRAME + HID + tid] = m;
    }
}

// ---------------------------------------------------------------------------
// Kernel 2: gi0 = frames @ Wih0^T + bih0 — wide GEMM over all 1024 rows.
// ---------------------------------------------------------------------------
#define GI0_GPB 8
__global__ void __launch_bounds__(192) gi0_kernel(const float* __restrict__ Wih0,
                                                  const float* __restrict__ bih0)
{
    extern __shared__ float smem[];
    float* W  = smem;                 // 192 x stride 100
    float* xf = smem + G3 * 100;      // 8 x 96

    const int tid = threadIdx.x;
    const int b0  = blockIdx.x * GI0_GPB;

    for (int i4 = tid; i4 < G3 * 24; i4 += 192) {
        int r = i4 / 24, c4 = i4 - (i4 / 24) * 24;
        *(float4*)(W + r * 100 + 4 * c4) = ld4(Wih0 + r * 96 + 4 * c4);
    }
    for (int i4 = tid; i4 < GI0_GPB * 24; i4 += 192)
        ((float4*)xf)[i4] = ((const float4*)(g_frames + (size_t)b0 * FRAME))[i4];
    __syncthreads();

    const int r = tid;
    float acc[GI0_GPB];
    float bi = bih0[r];
    #pragma unroll
    for (int gg = 0; gg < GI0_GPB; gg++) acc[gg] = bi;
    const float4* wr = (const float4*)(W + r * 100);
    #pragma unroll
    for (int f4 = 0; f4 < 24; f4++) {
        float4 w = wr[f4];
        #pragma unroll
        for (int gg = 0; gg < GI0_GPB; gg++) {
            float4 xv = ld4(xf + gg * 96 + 4 * f4);
            acc[gg] += w.x * xv.x + w.y * xv.y + w.z * xv.z + w.w * xv.w;
        }
    }
    #pragma unroll
    for (int gg = 0; gg < GI0_GPB; gg++)
        g_gi0[(size_t)(b0 + gg) * G3 + r] = acc[gg];
}

// ---------------------------------------------------------------------------
// Kernel 3: 2-layer GRU recurrence + MLP head. One block per batch row.
// 384 threads: 2 half-threads per output row -> wr[32] regs/thread (no spill),
// half-length serial chains; partials combined in smem by the gate threads.
// ---------------------------------------------------------------------------
__global__ void __launch_bounds__(384) gru_kernel(
    const float* __restrict__ Whh0, const float* __restrict__ bhh0,
    const float* __restrict__ Wih1, const float* __restrict__ bih1,
    const float* __restrict__ Whh1, const float* __restrict__ bhh1,
    const float* __restrict__ Wh1,  const float* __restrict__ bh1,
    const float* __restrict__ Wh2,  const float* __restrict__ bh2,
    float* __restrict__ out)
{
    __shared__ float gi[TT * G3];      // 3072
    __shared__ float seq[TT * GRUH];   // 1024
    __shared__ float hbuf[GRUH];       // 64
    __shared__ float ghp[2 * G3];      // 384 (partial gh, one per half)
    __shared__ float q[32];

    const int b    = blockIdx.x;
    const int tid  = threadIdx.x;
    const int row  = tid % G3;         // 0..191 (warps 0-5 half0, 6-11 half1)
    const int half = tid / G3;         // 0 or 1

    // ---- load gi0 for this batch row ----
    for (int i4 = tid; i4 < TT * G3 / 4; i4 += 384)
        ((float4*)gi)[i4] = ((const float4*)(g_gi0 + (size_t)b * TT * G3))[i4];
    if (tid < GRUH) hbuf[tid] = 0.f;

    // ---- cache half a Whh0 row ----
    float wr[32];
    {
        const float* wrow = Whh0 + row * GRUH + half * 32;
        #pragma unroll
        for (int i = 0; i < 8; i++) {
            float4 v = ld4g(wrow + 4 * i);
            wr[4*i] = v.x; wr[4*i+1] = v.y; wr[4*i+2] = v.z; wr[4*i+3] = v.w;
        }
    }
    float bh = (half == 0) ? __ldg(bhh0 + row) : 0.f;
    __syncthreads();

    // ---- layer 0 recurrence (writes seq) ----
    for (int t = 0; t < TT; t++) {
        const float* hb = hbuf + half * 32;
        float acc[4] = {0.f, 0.f, 0.f, 0.f};
        #pragma unroll
        for (int j = 0; j < 4; j++) {
            float4 ha = ld4(hb + 8 * j);
            float4 hc = ld4(hb + 8 * j + 4);
            acc[j] += wr[8*j  ]*ha.x + wr[8*j+1]*ha.y + wr[8*j+2]*ha.z + wr[8*j+3]*ha.w
                    + wr[8*j+4]*hc.x + wr[8*j+5]*hc.y + wr[8*j+6]*hc.z + wr[8*j+7]*hc.w;
        }
        ghp[half * G3 + row] = (acc[0] + acc[1]) + (acc[2] + acc[3]) + bh;
        __syncthreads();
        if (tid < GRUH) {
            float ghr = ghp[tid]       + ghp[G3 + tid];
            float ghz = ghp[64 + tid]  + ghp[G3 + 64 + tid];
            float ghn = ghp[128 + tid] + ghp[G3 + 128 + tid];
            float r = fast_sigmoid(gi[t * G3 + tid] + ghr);
            float z = fast_sigmoid(gi[t * G3 + GRUH + tid] + ghz);
            float n = fast_tanh(gi[t * G3 + 2 * GRUH + tid] + r * ghn);
            float hn = (1.f - z) * n + z * hbuf[tid];
            hbuf[tid] = hn;
            seq[t * GRUH + tid] = hn;
        }
        __syncthreads();
    }

    // ---- gi1 for all 16 steps: each half-thread does 8 timesteps ----
    {
        float acc8[8];
        float bi = __ldg(bih1 + row);
        #pragma unroll
        for (int t = 0; t < 8; t++) acc8[t] = bi;
        const float* wrow = Wih1 + row * GRUH;
        const int t0 = half * 8;
        #pragma unroll
        for (int f4 = 0; f4 < 16; f4++) {
            float4 w = ld4g(wrow + 4 * f4);
            #pragma unroll
            for (int t = 0; t < 8; t++) {
                float4 xv = ld4(seq + (t0 + t) * GRUH + 4 * f4);
                acc8[t] += w.x * xv.x + w.y * xv.y + w.z * xv.z + w.w * xv.w;
            }
        }
        #pragma unroll
        for (int t = 0; t < 8; t++) gi[(t0 + t) * G3 + row] = acc8[t];
    }

    // ---- switch to layer-1 weights ----
    {
        const float* wrow = Whh1 + row * GRUH + half * 32;
        #pragma unroll
        for (int i = 0; i < 8; i++) {
            float4 v = ld4g(wrow + 4 * i);
            wr[4*i] = v.x; wr[4*i+1] = v.y; wr[4*i+2] = v.z; wr[4*i+3] = v.w;
        }
    }
    bh = (half == 0) ? __ldg(bhh1 + row) : 0.f;
    if (tid < GRUH) hbuf[tid] = 0.f;
    __syncthreads();

    // ---- layer 1 recurrence (only final h needed) ----
    for (int t = 0; t < TT; t++) {
        const float* hb = hbuf + half * 32;
        float acc[4] = {0.f, 0.f, 0.f, 0.f};
        #pragma unroll
        for (int j = 0; j < 4; j++) {
            float4 ha = ld4(hb + 8 * j);
            float4 hc = ld4(hb + 8 * j + 4);
            acc[j] += wr[8*j  ]*ha.x + wr[8*j+1]*ha.y + wr[8*j+2]*ha.z + wr[8*j+3]*ha.w
                    + wr[8*j+4]*hc.x + wr[8*j+5]*hc.y + wr[8*j+6]*hc.z + wr[8*j+7]*hc.w;
        }
        ghp[half * G3 + row] = (acc[0] + acc[1]) + (acc[2] + acc[3]) + bh;
        __syncthreads();
        if (tid < GRUH) {
            float ghr = ghp[tid]       + ghp[G3 + tid];
            float ghz = ghp[64 + tid]  + ghp[G3 + 64 + tid];
            float ghn = ghp[128 + tid] + ghp[G3 + 128 + tid];
            float r = fast_sigmoid(gi[t * G3 + tid] + ghr);
            float z = fast_sigmoid(gi[t * G3 + GRUH + tid] + ghz);
            float n = fast_tanh(gi[t * G3 + 2 * GRUH + tid] + r * ghn);
            hbuf[tid] = (1.f - z) * n + z * hbuf[tid];
        }
        __syncthreads();
    }

    // ---- MLP head ----
    if (tid < 32) {
        float acc = __ldg(bh1 + tid);
        #pragma unroll
        for (int u = 0; u < GRUH; u++) acc += hbuf[u] * __ldg(Wh1 + u * 32 + tid);
        q[tid] = fmaxf(acc, 0.f);
    }
    __syncthreads();
    if (tid == 0) {
        float acc = __ldg(bh2);
        #pragma unroll
        for (int m = 0; m < 32; m++) acc += q[m] * __ldg(Wh2 + m);
        out[b] = acc;
    }
}

// ---------------------------------------------------------------------------
extern "C" void kernel_launch(void* const* d_in, const int* in_sizes, int n_in,
                              void* d_out, int out_size)
{
    const float* x    = (const float*)d_in[0];
    const float* W1   = (const float*)d_in[3];
    const float* as1  = (const float*)d_in[4];
    const float* ad1  = (const float*)d_in[5];
    const float* b1   = (const float*)d_in[6];
    const float* W2   = (const float*)d_in[7];
    const float* as2  = (const float*)d_in[8];
    const float* ad2  = (const float*)d_in[9];
    const float* b2   = (const float*)d_in[10];
    const float* Wih0 = (const float*)d_in[11];
    const float* Whh0 = (const float*)d_in[12];
    const float* bih0 = (const float*)d_in[13];
    const float* bhh0 = (const float*)d_in[14];
    const float* Wih1 = (const float*)d_in[15];
    const float* Whh1 = (const float*)d_in[16];
    const float* bih1 = (const float*)d_in[17];
    const float* bhh1 = (const float*)d_in[18];
    const float* Wh1  = (const float*)d_in[19];
    const float* bh1  = (const float*)d_in[20];
    const float* Wh2  = (const float*)d_in[21];
    const float* bh2  = (const float*)d_in[22];

    const int GAT_SMEM = 11600 * 4;   // 46400 B -> 4 blocks/SM
    const int GI0_SMEM = (G3 * 100 + GI0_GPB * FRAME) * 4;

    static bool attrs_set = false;
    if (!attrs_set) {
        cudaFuncSetAttribute(gat_kernel, cudaFuncAttributeMaxDynamicSharedMemorySize, GAT_SMEM);
        cudaFuncSetAttribute(gi0_kernel, cudaFuncAttributeMaxDynamicSharedMemorySize, GI0_SMEM);
        attrs_set = true;
    }

    gat_kernel<<<NGRAPH, 256, GAT_SMEM>>>(x, W1, as1, ad1, b1, W2, as2, ad2, b2);
    gi0_kernel<<<NGRAPH / GI0_GPB, 192, GI0_SMEM>>>(Wih0, bih0);
    gru_kernel<<<BB, 384>>>(Whh0, bhh0, Wih1, bih1, Whh1, bhh1,
                            Wh1, bh1, Wh2, bh2, (float*)d_out);
}